// round 9
// baseline (speedup 1.0000x reference)
#include <cuda_runtime.h>
#include <cuda_bf16.h>

#define NB 16
#define LL 1024
#define DH 256
#define NEGINF (-1e30f)
#define FLT_LOW (-3.4e38f)

// ---------------- scratch (static device globals; no allocation) -------------
__device__ float g_sim[NB * LL * LL];                 // 67 MB scores
__device__ __nv_bfloat16 g_PWhi[NB * LL * DH];
__device__ __nv_bfloat16 g_PWlo[NB * LL * DH];
__device__ __nv_bfloat16 g_Hhi[NB * LL * DH];
__device__ __nv_bfloat16 g_Hlo[NB * LL * DH];
__device__ __nv_bfloat16 g_Phi[NB * LL * DH];
__device__ __nv_bfloat16 g_Plo[NB * LL * DH];
__device__ __nv_bfloat16 g_Wthi[DH * DH];             // W^T split: [e][d]
__device__ __nv_bfloat16 g_Wtlo[DH * DH];
__device__ float g_rowmax[NB * LL];
__device__ float g_rowinv[NB * LL];
__device__ float g_colpart[NB * 64 * LL];             // 64 p-chunks per batch
__device__ float g_pvec[NB * DH];

union BF8 { uint4 v; __nv_bfloat16 h[8]; };
union BF4 { uint2 v; __nv_bfloat16 h[4]; };
union BF2 { unsigned u; __nv_bfloat16 h[2]; };

__device__ __forceinline__ void mma_bf16(float d[4], const unsigned a[4], const unsigned b[2]) {
    asm volatile(
        "mma.sync.aligned.m16n8k16.row.col.f32.bf16.bf16.f32 "
        "{%0,%1,%2,%3}, {%4,%5,%6,%7}, {%8,%9}, {%0,%1,%2,%3};"
        : "+f"(d[0]), "+f"(d[1]), "+f"(d[2]), "+f"(d[3])
        : "r"(a[0]), "r"(a[1]), "r"(a[2]), "r"(a[3]), "r"(b[0]), "r"(b[1]));
}

__device__ __forceinline__ unsigned sm32(const void* p) {
    return (unsigned)__cvta_generic_to_shared(p);
}
__device__ __forceinline__ void ldsm4(unsigned* r, unsigned a) {
    asm volatile("ldmatrix.sync.aligned.m8n8.x4.shared.b16 {%0,%1,%2,%3}, [%4];"
                 : "=r"(r[0]), "=r"(r[1]), "=r"(r[2]), "=r"(r[3]) : "r"(a));
}
__device__ __forceinline__ void ldsm4t(unsigned* r, unsigned a) {
    asm volatile("ldmatrix.sync.aligned.m8n8.x4.trans.shared.b16 {%0,%1,%2,%3}, [%4];"
                 : "=r"(r[0]), "=r"(r[1]), "=r"(r[2]), "=r"(r[3]) : "r"(a));
}

__device__ __forceinline__ void split_bf16(float f, __nv_bfloat16& hi, __nv_bfloat16& lo) {
    hi = __float2bfloat16(f);
    lo = __float2bfloat16(f - __bfloat162float(hi));
}

// =============================================================================
// Kernels CVT
// =============================================================================
__global__ void k_cvtH(const float* __restrict__ X) {
    size_t i = ((size_t)blockIdx.x * 256 + threadIdx.x) * 4;
    float4 v = *(const float4*)(X + i);
    BF4 hi, lo;
    split_bf16(v.x, hi.h[0], lo.h[0]);
    split_bf16(v.y, hi.h[1], lo.h[1]);
    split_bf16(v.z, hi.h[2], lo.h[2]);
    split_bf16(v.w, hi.h[3], lo.h[3]);
    *(uint2*)&g_Hhi[i] = hi.v;
    *(uint2*)&g_Hlo[i] = lo.v;
}
__global__ void k_cvtP(const float* __restrict__ X) {
    size_t i = ((size_t)blockIdx.x * 256 + threadIdx.x) * 4;
    float4 v = *(const float4*)(X + i);
    BF4 hi, lo;
    split_bf16(v.x, hi.h[0], lo.h[0]);
    split_bf16(v.y, hi.h[1], lo.h[1]);
    split_bf16(v.z, hi.h[2], lo.h[2]);
    split_bf16(v.w, hi.h[3], lo.h[3]);
    *(uint2*)&g_Phi[i] = hi.v;
    *(uint2*)&g_Plo[i] = lo.v;
}
__global__ void k_cvtW(const float* __restrict__ W) {
    int idx = blockIdx.x * 256 + threadIdx.x;     // 65536
    int d = idx >> 8, e = idx & 255;
    float v = W[idx];
    __nv_bfloat16 hi, lo;
    split_bf16(v, hi, lo);
    g_Wthi[e * DH + d] = hi;
    g_Wtlo[e * DH + d] = lo;
}

// =============================================================================
// Kernel A (tensor): PW = P @ W — split-bf16 3-product, ldmatrix fragments
// =============================================================================
__global__ __launch_bounds__(256) void k_pw_mma() {
    __shared__ __align__(16) __nv_bfloat16 Ah[128][40], Al[128][40];
    __shared__ __align__(16) __nv_bfloat16 Bh[128][40], Bl[128][40];
    const int bm = blockIdx.y * 128, bn = blockIdx.x * 128;
    const int tid = threadIdx.x, warp = tid >> 5, lane = tid & 31;
    const int wm = (warp >> 2) * 64, wn = (warp & 3) * 32;
    const int gid = lane >> 2, tig = lane & 3;
    const int lrow = tid >> 1, lseg = (tid & 1) * 16;
    const int arow = wm + (lane & 15), acol = (lane >> 4) * 8;
    const int bro  = (lane & 7) + ((lane >> 4) & 1) * 8;
    const int bco  = ((lane >> 3) & 1) * 8;

    const size_t abase = (size_t)(bm + lrow) * DH + lseg;
    const size_t bbase = (size_t)(bn + lrow) * DH + lseg;

    float acc[4][4][4];
#pragma unroll
    for (int mt = 0; mt < 4; mt++)
#pragma unroll
        for (int nt = 0; nt < 4; nt++)
#pragma unroll
            for (int e = 0; e < 4; e++) acc[mt][nt][e] = 0.0f;

    for (int k0 = 0; k0 < DH; k0 += 32) {
        uint4 ah0 = *(const uint4*)&g_Phi[abase + k0];
        uint4 ah1 = *(const uint4*)&g_Phi[abase + k0 + 8];
        uint4 al0 = *(const uint4*)&g_Plo[abase + k0];
        uint4 al1 = *(const uint4*)&g_Plo[abase + k0 + 8];
        uint4 bh0 = *(const uint4*)&g_Wthi[bbase + k0];
        uint4 bh1 = *(const uint4*)&g_Wthi[bbase + k0 + 8];
        uint4 bl0 = *(const uint4*)&g_Wtlo[bbase + k0];
        uint4 bl1 = *(const uint4*)&g_Wtlo[bbase + k0 + 8];
        __syncthreads();
        *(uint4*)&Ah[lrow][lseg] = ah0; *(uint4*)&Ah[lrow][lseg + 8] = ah1;
        *(uint4*)&Al[lrow][lseg] = al0; *(uint4*)&Al[lrow][lseg + 8] = al1;
        *(uint4*)&Bh[lrow][lseg] = bh0; *(uint4*)&Bh[lrow][lseg + 8] = bh1;
        *(uint4*)&Bl[lrow][lseg] = bl0; *(uint4*)&Bl[lrow][lseg + 8] = bl1;
        __syncthreads();
#pragma unroll
        for (int ks = 0; ks < 32; ks += 16) {
            unsigned afh[4][4], afl[4][4];
#pragma unroll
            for (int mt = 0; mt < 4; mt++) {
                ldsm4(afh[mt], sm32(&Ah[arow + mt * 16][ks + acol]));
                ldsm4(afl[mt], sm32(&Al[arow + mt * 16][ks + acol]));
            }
#pragma unroll
            for (int p = 0; p < 2; p++) {
                unsigned bh4[4], bl4[4];
                ldsm4(bh4, sm32(&Bh[wn + p * 16 + bro][ks + bco]));
                ldsm4(bl4, sm32(&Bl[wn + p * 16 + bro][ks + bco]));
#pragma unroll
                for (int s = 0; s < 2; s++) {
                    int nt = p * 2 + s;
                    unsigned bfh[2] = {bh4[2 * s], bh4[2 * s + 1]};
                    unsigned bfl[2] = {bl4[2 * s], bl4[2 * s + 1]};
#pragma unroll
                    for (int mt = 0; mt < 4; mt++) {
                        mma_bf16(acc[mt][nt], afh[mt], bfh);
                        mma_bf16(acc[mt][nt], afh[mt], bfl);
                        mma_bf16(acc[mt][nt], afl[mt], bfh);
                    }
                }
            }
        }
    }
#pragma unroll
    for (int mt = 0; mt < 4; mt++) {
        int r0 = bm + wm + mt * 16 + gid, r1 = r0 + 8;
#pragma unroll
        for (int nt = 0; nt < 4; nt++) {
            int c = bn + wn + nt * 8 + tig * 2;
            float* d = acc[mt][nt];
            BF2 h0, l0, h1, l1;
            split_bf16(d[0], h0.h[0], l0.h[0]);
            split_bf16(d[1], h0.h[1], l0.h[1]);
            split_bf16(d[2], h1.h[0], l1.h[0]);
            split_bf16(d[3], h1.h[1], l1.h[1]);
            *(unsigned*)&g_PWhi[(size_t)r0 * DH + c] = h0.u;
            *(unsigned*)&g_PWlo[(size_t)r0 * DH + c] = l0.u;
            *(unsigned*)&g_PWhi[(size_t)r1 * DH + c] = h1.u;
            *(unsigned*)&g_PWlo[(size_t)r1 * DH + c] = l1.u;
        }
    }
}

// =============================================================================
// Kernel B: sim[b] = PW[b] @ H[b]^T + bias + mask — ldmatrix fragments
// =============================================================================
__global__ __launch_bounds__(256) void k_sim(const int* __restrict__ pmask,
                                             const int* __restrict__ hmask,
                                             const float* __restrict__ bias) {
    __shared__ __align__(16) __nv_bfloat16 Ah[128][40], Al[128][40];
    __shared__ __align__(16) __nv_bfloat16 Bh[128][40], Bl[128][40];
    const int b = blockIdx.z;
    const int bm = blockIdx.y * 128, bn = blockIdx.x * 128;
    const int tid = threadIdx.x, warp = tid >> 5, lane = tid & 31;
    const int wm = (warp >> 2) * 64, wn = (warp & 3) * 32;
    const int gid = lane >> 2, tig = lane & 3;
    const int lrow = tid >> 1, lseg = (tid & 1) * 16;
    const int arow = wm + (lane & 15), acol = (lane >> 4) * 8;
    const int bro  = (lane & 7) + ((lane >> 4) & 1) * 8;
    const int bco  = ((lane >> 3) & 1) * 8;

    const size_t abase = ((size_t)b * LL + bm + lrow) * DH + lseg;
    const size_t bbase = ((size_t)b * LL + bn + lrow) * DH + lseg;

    float acc[4][4][4];
#pragma unroll
    for (int mt = 0; mt < 4; mt++)
#pragma unroll
        for (int nt = 0; nt < 4; nt++)
#pragma unroll
            for (int e = 0; e < 4; e++) acc[mt][nt][e] = 0.0f;

    for (int k0 = 0; k0 < DH; k0 += 32) {
        uint4 ah0 = *(const uint4*)&g_PWhi[abase + k0];
        uint4 ah1 = *(const uint4*)&g_PWhi[abase + k0 + 8];
        uint4 al0 = *(const uint4*)&g_PWlo[abase + k0];
        uint4 al1 = *(const uint4*)&g_PWlo[abase + k0 + 8];
        uint4 bh0 = *(const uint4*)&g_Hhi[bbase + k0];
        uint4 bh1 = *(const uint4*)&g_Hhi[bbase + k0 + 8];
        uint4 bl0 = *(const uint4*)&g_Hlo[bbase + k0];
        uint4 bl1 = *(const uint4*)&g_Hlo[bbase + k0 + 8];
        __syncthreads();
        *(uint4*)&Ah[lrow][lseg] = ah0; *(uint4*)&Ah[lrow][lseg + 8] = ah1;
        *(uint4*)&Al[lrow][lseg] = al0; *(uint4*)&Al[lrow][lseg + 8] = al1;
        *(uint4*)&Bh[lrow][lseg] = bh0; *(uint4*)&Bh[lrow][lseg + 8] = bh1;
        *(uint4*)&Bl[lrow][lseg] = bl0; *(uint4*)&Bl[lrow][lseg + 8] = bl1;
        __syncthreads();
#pragma unroll
        for (int ks = 0; ks < 32; ks += 16) {
            unsigned afh[4][4], afl[4][4];
#pragma unroll
            for (int mt = 0; mt < 4; mt++) {
                ldsm4(afh[mt], sm32(&Ah[arow + mt * 16][ks + acol]));
                ldsm4(afl[mt], sm32(&Al[arow + mt * 16][ks + acol]));
            }
#pragma unroll
            for (int p = 0; p < 2; p++) {
                unsigned bh4[4], bl4[4];
                ldsm4(bh4, sm32(&Bh[wn + p * 16 + bro][ks + bco]));
                ldsm4(bl4, sm32(&Bl[wn + p * 16 + bro][ks + bco]));
#pragma unroll
                for (int s = 0; s < 2; s++) {
                    int nt = p * 2 + s;
                    unsigned bfh[2] = {bh4[2 * s], bh4[2 * s + 1]};
                    unsigned bfl[2] = {bl4[2 * s], bl4[2 * s + 1]};
#pragma unroll
                    for (int mt = 0; mt < 4; mt++) {
                        mma_bf16(acc[mt][nt], afh[mt], bfh);
                        mma_bf16(acc[mt][nt], afh[mt], bfl);
                        mma_bf16(acc[mt][nt], afl[mt], bfh);
                    }
                }
            }
        }
    }

    const float bb = bias[0];
#pragma unroll
    for (int mt = 0; mt < 4; mt++) {
        int r0 = bm + wm + mt * 16 + gid, r1 = r0 + 8;
        float pm0 = (float)pmask[b * LL + r0];
        float pm1 = (float)pmask[b * LL + r1];
#pragma unroll
        for (int nt = 0; nt < 4; nt++) {
            int c = bn + wn + nt * 8 + tig * 2;
            float hm0 = (float)hmask[b * LL + c];
            float hm1 = (float)hmask[b * LL + c + 1];
            float* d = acc[mt][nt];
            float2 v0 = make_float2(d[0] + bb + (1.0f - pm0 * hm0) * NEGINF,
                                    d[1] + bb + (1.0f - pm0 * hm1) * NEGINF);
            float2 v1 = make_float2(d[2] + bb + (1.0f - pm1 * hm0) * NEGINF,
                                    d[3] + bb + (1.0f - pm1 * hm1) * NEGINF);
            *(float2*)&g_sim[((size_t)b * LL + r0) * LL + c] = v0;
            *(float2*)&g_sim[((size_t)b * LL + r1) * LL + c] = v1;
        }
    }
}

// =============================================================================
// Kernel C (fused): rowmax/rowinv + colmax partials in ONE pass over sim
// =============================================================================
__global__ __launch_bounds__(256) void k_stats() {
    const int blk = blockIdx.x;                    // 0..127
    const int warp = threadIdx.x >> 5, lane = threadIdx.x & 31;
    const int rowbase = blk * 128 + warp * 16;
    const int b = blk >> 3;

    float4 cm[8];
#pragma unroll
    for (int s = 0; s < 8; s++) cm[s] = make_float4(FLT_LOW, FLT_LOW, FLT_LOW, FLT_LOW);

    for (int r = 0; r < 16; r++) {
        const int row = rowbase + r;
        const float* s = g_sim + (size_t)row * LL + lane * 4;
        float4 v[8];
#pragma unroll
        for (int sg = 0; sg < 8; sg++) v[sg] = *(const float4*)(s + sg * 128);
        float m = FLT_LOW;
#pragma unroll
        for (int sg = 0; sg < 8; sg++) {
            m = fmaxf(m, fmaxf(fmaxf(v[sg].x, v[sg].y), fmaxf(v[sg].z, v[sg].w)));
            cm[sg].x = fmaxf(cm[sg].x, v[sg].x);
            cm[sg].y = fmaxf(cm[sg].y, v[sg].y);
            cm[sg].z = fmaxf(cm[sg].z, v[sg].z);
            cm[sg].w = fmaxf(cm[sg].w, v[sg].w);
        }
#pragma unroll
        for (int o = 16; o > 0; o >>= 1) m = fmaxf(m, __shfl_xor_sync(0xffffffffu, m, o));
        float sum = 0.0f;
#pragma unroll
        for (int sg = 0; sg < 8; sg++)
            sum += __expf(v[sg].x - m) + __expf(v[sg].y - m)
                 + __expf(v[sg].z - m) + __expf(v[sg].w - m);
#pragma unroll
        for (int o = 16; o > 0; o >>= 1) sum += __shfl_xor_sync(0xffffffffu, sum, o);
        if (lane == 0) {
            g_rowmax[row] = m;
            g_rowinv[row] = 1.0f / sum;
        }
    }
    const int chunk = (blk & 7) * 8 + warp;        // 0..63 within batch
    float* cp = g_colpart + ((size_t)b * 64 + chunk) * LL + lane * 4;
#pragma unroll
    for (int sg = 0; sg < 8; sg++) *(float4*)(cp + sg * 128) = cm[sg];
}

// =============================================================================
// Kernel D: aligned_hyp[b] = softmax(sim[b]) @ H[b]
// A: on-the-fly probs (ldmatrix). B: H stored untransposed, ldmatrix.trans.
// =============================================================================
__global__ __launch_bounds__(256) void k_av(float* __restrict__ out) {
    __shared__ __align__(16) __nv_bfloat16 Ah[128][40], Al[128][40];
    __shared__ __align__(16) __nv_bfloat16 Bhs[32][136], Bls[32][136];
    const int b = blockIdx.z;
    const int bm = blockIdx.y * 128, bn = blockIdx.x * 128;   // bn over DH
    const int tid = threadIdx.x, warp = tid >> 5, lane = tid & 31;
    const int wm = (warp >> 2) * 64, wn = (warp & 3) * 32;
    const int gid = lane >> 2, tig = lane & 3;
    const int lrow = tid >> 1, lseg = (tid & 1) * 16;
    const int arow = wm + (lane & 15), acol = (lane >> 4) * 8;
    const int tkr = (lane & 7) + ((lane >> 3) & 1) * 8;        // k-row within chunk
    const int tdc = ((lane >> 4) & 1) * 8;                     // d-col offset
    const int qr = tid >> 3, dc = (tid & 7) * 16;              // H tile loader

    const float rm = g_rowmax[b * LL + bm + lrow];
    const float ri = g_rowinv[b * LL + bm + lrow];
    const float* sp = &g_sim[((size_t)b * LL + bm + lrow) * LL + lseg];

    float acc[4][4][4];
#pragma unroll
    for (int mt = 0; mt < 4; mt++)
#pragma unroll
        for (int nt = 0; nt < 4; nt++)
#pragma unroll
            for (int e = 0; e < 4; e++) acc[mt][nt][e] = 0.0f;

    for (int k0 = 0; k0 < LL; k0 += 32) {
        float4 f0 = *(const float4*)(sp + k0);
        float4 f1 = *(const float4*)(sp + k0 + 4);
        float4 f2 = *(const float4*)(sp + k0 + 8);
        float4 f3 = *(const float4*)(sp + k0 + 12);
        size_t hb = ((size_t)b * LL + k0 + qr) * DH + bn + dc;
        uint4 hh0 = *(const uint4*)&g_Hhi[hb];
        uint4 hh1 = *(const uint4*)&g_Hhi[hb + 8];
        uint4 hl0 = *(const uint4*)&g_Hlo[hb];
        uint4 hl1 = *(const uint4*)&g_Hlo[hb + 8];
        __syncthreads();
        {
            float e[16] = {f0.x, f0.y, f0.z, f0.w, f1.x, f1.y, f1.z, f1.w,
                           f2.x, f2.y, f2.z, f2.w, f3.x, f3.y, f3.z, f3.w};
            BF8 phi0, phi1, plo0, plo1;
#pragma unroll
            for (int i = 0; i < 8; i++) {
                float p0 = __expf(e[i] - rm) * ri;
                float p1 = __expf(e[8 + i] - rm) * ri;
                split_bf16(p0, phi0.h[i], plo0.h[i]);
                split_bf16(p1, phi1.h[i], plo1.h[i]);
            }
            *(uint4*)&Ah[lrow][lseg] = phi0.v; *(uint4*)&Ah[lrow][lseg + 8] = phi1.v;
            *(uint4*)&Al[lrow][lseg] = plo0.v; *(uint4*)&Al[lrow][lseg + 8] = plo1.v;
        }
        *(uint4*)&Bhs[qr][dc]     = hh0;
        *(uint4*)&Bhs[qr][dc + 8] = hh1;
        *(uint4*)&Bls[qr][dc]     = hl0;
        *(uint4*)&Bls[qr][dc + 8] = hl1;
        __syncthreads();
#pragma unroll
        for (int ks = 0; ks < 32; ks += 16) {
            unsigned afh[4][4], afl[4][4];
#pragma unroll
            for (int mt = 0; mt < 4; mt++) {
                ldsm4(afh[mt], sm32(&Ah[arow + mt * 16][ks + acol]));
                ldsm4(afl[mt], sm32(&Al[arow + mt * 16][ks + acol]));
            }
#pragma unroll
            for (int p = 0; p < 2; p++) {
                unsigned bh4[4], bl4[4];
                ldsm4t(bh4, sm32(&Bhs[ks + tkr][wn + p * 16 + tdc]));
                ldsm4t(bl4, sm32(&Bls[ks + tkr][wn + p * 16 + tdc]));
#pragma unroll
                for (int s = 0; s < 2; s++) {
                    int nt = p * 2 + s;
                    unsigned bfh[2] = {bh4[2 * s], bh4[2 * s + 1]};
                    unsigned bfl[2] = {bl4[2 * s], bl4[2 * s + 1]};
#pragma unroll
                    for (int mt = 0; mt < 4; mt++) {
                        mma_bf16(acc[mt][nt], afh[mt], bfh);
                        mma_bf16(acc[mt][nt], afh[mt], bfl);
                        mma_bf16(acc[mt][nt], afl[mt], bfh);
                    }
                }
            }
        }
    }
#pragma unroll
    for (int mt = 0; mt < 4; mt++) {
        int r0 = bm + wm + mt * 16 + gid, r1 = r0 + 8;
#pragma unroll
        for (int nt = 0; nt < 4; nt++) {
            int c = bn + wn + nt * 8 + tig * 2;
            float* d = acc[mt][nt];
            *(float2*)&out[((size_t)b * LL + r0) * DH + c] = make_float2(d[0], d[1]);
            *(float2*)&out[((size_t)b * LL + r1) * DH + c] = make_float2(d[2], d[3]);
        }
    }
}

// =============================================================================
// Kernel E: per batch — softmax(colmax over 64 partials) @ P -> g_pvec
// =============================================================================
__global__ __launch_bounds__(256) void k_premise(const float* __restrict__ P) {
    const int b = blockIdx.x;
    const int t = threadIdx.x;
    __shared__ float prob[LL];
    __shared__ float red[8];
    float loc[4];
#pragma unroll
    for (int c = 0; c < 4; c++) {
        int q = c * 256 + t;
        float m = FLT_LOW;
        for (int j = 0; j < 64; j++)
            m = fmaxf(m, g_colpart[((size_t)b * 64 + j) * LL + q]);
        loc[c] = m;
    }
    float mx = fmaxf(fmaxf(loc[0], loc[1]), fmaxf(loc[2], loc[3]));
#pragma unroll
    for (int o = 16; o > 0; o >>= 1) mx = fmaxf(mx, __shfl_xor_sync(0xffffffffu, mx, o));
    const int w = t >> 5, lane = t & 31;
    if (lane == 0) red[w] = mx;
    __syncthreads();
    mx = red[0];
#pragma unroll
    for (int j = 1; j < 8; j++) mx = fmaxf(mx, red[j]);

    float se = 0.0f;
#pragma unroll
    for (int c = 0; c < 4; c++) {
        float e = __expf(loc[c] - mx);
        prob[c * 256 + t] = e;
        se += e;
    }
#pragma unroll
    for (int o = 16; o > 0; o >>= 1) se += __shfl_xor_sync(0xffffffffu, se, o);
    __syncthreads();
    if (lane == 0) red[w] = se;
    __syncthreads();
    float tot = 0.0f;
#pragma unroll
    for (int j = 0; j < 8; j++) tot += red[j];
    const float inv = 1.0f / tot;

    const float* Pb = P + (size_t)b * LL * DH + t;
    float acc = 0.0f;
#pragma unroll 8
    for (int q = 0; q < LL; q++)
        acc = fmaf(prob[q], Pb[(size_t)q * DH], acc);
    g_pvec[b * DH + t] = acc * inv;
}

// =============================================================================
// Kernel F: broadcast g_pvec -> out[0 : NB*LL*DH)
// =============================================================================
__global__ void k_bcast(float* __restrict__ out) {
    int idx = (blockIdx.x * 256 + threadIdx.x) * 4;
    int b = idx >> 18;
    int d = idx & (DH - 1);
    float4 v = *(const float4*)&g_pvec[b * DH + d];
    *(float4*)&out[idx] = v;
}

// =============================================================================
extern "C" void kernel_launch(void* const* d_in, const int* in_sizes, int n_in,
                              void* d_out, int out_size) {
    const float* P    = (const float*)d_in[0];
    const float* Hh   = (const float*)d_in[1];
    const int*   pm   = (const int*)d_in[2];
    const int*   hm   = (const int*)d_in[3];
    const float* W    = (const float*)d_in[4];
    const float* bias = (const float*)d_in[5];
    float* out = (float*)d_out;

    k_cvtH    <<<(NB * LL * DH) / (256 * 4), 256>>>(Hh);
    k_cvtP    <<<(NB * LL * DH) / (256 * 4), 256>>>(P);
    k_cvtW    <<<DH * DH / 256, 256>>>(W);
    k_pw_mma  <<<dim3(DH / 128, (NB * LL) / 128), 256>>>();
    k_sim     <<<dim3(LL / 128, LL / 128, NB), 256>>>(pm, hm, bias);
    k_stats   <<<(NB * LL) / 128, 256>>>();
    k_av      <<<dim3(DH / 128, LL / 128, NB), 256>>>(out + (size_t)NB * LL * DH);
    k_premise <<<NB, 256>>>(P);
    k_bcast   <<<(NB * LL * DH) / (256 * 4), 256>>>(out);
}

// round 10
// speedup vs baseline: 1.2434x; 1.2434x over previous
#include <cuda_runtime.h>
#include <cuda_bf16.h>

#define NB 16
#define LL 1024
#define DH 256
#define NEGINF (-1e30f)
#define FLT_LOW (-3.4e38f)

// ---------------- scratch (static device globals; no allocation) -------------
__device__ float g_sim[NB * LL * LL];                 // 67 MB scores
__device__ __nv_bfloat16 g_PWhi[NB * LL * DH];
__device__ __nv_bfloat16 g_PWlo[NB * LL * DH];
__device__ __nv_bfloat16 g_Hhi[NB * LL * DH];
__device__ __nv_bfloat16 g_Hlo[NB * LL * DH];
__device__ __nv_bfloat16 g_Phi[NB * LL * DH];
__device__ __nv_bfloat16 g_Plo[NB * LL * DH];
__device__ __nv_bfloat16 g_Wthi[DH * DH];             // W^T split: [e][d]
__device__ __nv_bfloat16 g_Wtlo[DH * DH];
__device__ float g_rowmax[NB * LL];
__device__ float g_rowinv[NB * LL];
__device__ float g_colpart[NB * 64 * LL];             // 64 p-chunks per batch
__device__ float g_pvec[NB * DH];

union BF8 { uint4 v; __nv_bfloat16 h[8]; };
union BF4 { uint2 v; __nv_bfloat16 h[4]; };
union BF2 { unsigned u; __nv_bfloat16 h[2]; };

__device__ __forceinline__ void mma_bf16(float d[4], const unsigned a[4], const unsigned b[2]) {
    asm volatile(
        "mma.sync.aligned.m16n8k16.row.col.f32.bf16.bf16.f32 "
        "{%0,%1,%2,%3}, {%4,%5,%6,%7}, {%8,%9}, {%0,%1,%2,%3};"
        : "+f"(d[0]), "+f"(d[1]), "+f"(d[2]), "+f"(d[3])
        : "r"(a[0]), "r"(a[1]), "r"(a[2]), "r"(a[3]), "r"(b[0]), "r"(b[1]));
}

__device__ __forceinline__ unsigned sm32(const void* p) {
    return (unsigned)__cvta_generic_to_shared(p);
}
__device__ __forceinline__ void ldsm4(unsigned* r, unsigned a) {
    asm volatile("ldmatrix.sync.aligned.m8n8.x4.shared.b16 {%0,%1,%2,%3}, [%4];"
                 : "=r"(r[0]), "=r"(r[1]), "=r"(r[2]), "=r"(r[3]) : "r"(a));
}
__device__ __forceinline__ void ldsm4t(unsigned* r, unsigned a) {
    asm volatile("ldmatrix.sync.aligned.m8n8.x4.trans.shared.b16 {%0,%1,%2,%3}, [%4];"
                 : "=r"(r[0]), "=r"(r[1]), "=r"(r[2]), "=r"(r[3]) : "r"(a));
}
__device__ __forceinline__ void cpa16(void* dst, const void* src) {
    asm volatile("cp.async.cg.shared.global [%0], [%1], 16;"
                 :: "r"(sm32(dst)), "l"(src));
}
#define CP_COMMIT asm volatile("cp.async.commit_group;")
#define CP_WAIT0  asm volatile("cp.async.wait_group 0;")

__device__ __forceinline__ void split_bf16(float f, __nv_bfloat16& hi, __nv_bfloat16& lo) {
    hi = __float2bfloat16(f);
    lo = __float2bfloat16(f - __bfloat162float(hi));
}

// =============================================================================
// Kernels CVT
// =============================================================================
__global__ void k_cvtH(const float* __restrict__ X) {
    size_t i = ((size_t)blockIdx.x * 256 + threadIdx.x) * 4;
    float4 v = *(const float4*)(X + i);
    BF4 hi, lo;
    split_bf16(v.x, hi.h[0], lo.h[0]);
    split_bf16(v.y, hi.h[1], lo.h[1]);
    split_bf16(v.z, hi.h[2], lo.h[2]);
    split_bf16(v.w, hi.h[3], lo.h[3]);
    *(uint2*)&g_Hhi[i] = hi.v;
    *(uint2*)&g_Hlo[i] = lo.v;
}
__global__ void k_cvtP(const float* __restrict__ X) {
    size_t i = ((size_t)blockIdx.x * 256 + threadIdx.x) * 4;
    float4 v = *(const float4*)(X + i);
    BF4 hi, lo;
    split_bf16(v.x, hi.h[0], lo.h[0]);
    split_bf16(v.y, hi.h[1], lo.h[1]);
    split_bf16(v.z, hi.h[2], lo.h[2]);
    split_bf16(v.w, hi.h[3], lo.h[3]);
    *(uint2*)&g_Phi[i] = hi.v;
    *(uint2*)&g_Plo[i] = lo.v;
}
__global__ void k_cvtW(const float* __restrict__ W) {
    int idx = blockIdx.x * 256 + threadIdx.x;     // 65536
    int d = idx >> 8, e = idx & 255;
    float v = W[idx];
    __nv_bfloat16 hi, lo;
    split_bf16(v, hi, lo);
    g_Wthi[e * DH + d] = hi;
    g_Wtlo[e * DH + d] = lo;
}

// =============================================================================
// Shared GEMM body (NT, split-bf16 3-product, cp.async double-buffer, ldmatrix)
// A rows from Ag (hi/lo), B rows from Bg (hi/lo), K = kdim.
// Dynamic smem: 2 stages x [Ah|Al|Bh|Bl] each 128x40 halfwords.
// =============================================================================
#define STG (4 * 128 * 40)        // halfwords per stage
#define ARR (128 * 40)

template<int KDIM>
__device__ __forceinline__ void gemm_nt_body(
    __nv_bfloat16* sm,
    const __nv_bfloat16* __restrict__ Aghi, const __nv_bfloat16* __restrict__ Aglo,
    const __nv_bfloat16* __restrict__ Bghi, const __nv_bfloat16* __restrict__ Bglo,
    size_t abase, size_t bbase, float acc[4][4][4],
    int wm, int wn, int lane)
{
    const int tid = threadIdx.x;
    const int lrow = tid >> 1, lseg = (tid & 1) * 16;
    const int arow = wm + (lane & 15), acol = (lane >> 4) * 8;
    const int bro  = (lane & 7) + ((lane >> 4) & 1) * 8;
    const int bco  = ((lane >> 3) & 1) * 8;
    const int soff = lrow * 40 + lseg;

    // prefetch k0 = 0 into stage 0
    {
        __nv_bfloat16* st = sm;
        cpa16(st + soff,              Aghi + abase);
        cpa16(st + soff + 8,          Aghi + abase + 8);
        cpa16(st + ARR + soff,        Aglo + abase);
        cpa16(st + ARR + soff + 8,    Aglo + abase + 8);
        cpa16(st + 2*ARR + soff,      Bghi + bbase);
        cpa16(st + 2*ARR + soff + 8,  Bghi + bbase + 8);
        cpa16(st + 3*ARR + soff,      Bglo + bbase);
        cpa16(st + 3*ARR + soff + 8,  Bglo + bbase + 8);
        CP_COMMIT;
    }
    int s = 0;
    for (int k0 = 0; k0 < KDIM; k0 += 32, s ^= 1) {
        CP_WAIT0;
        __syncthreads();
        if (k0 + 32 < KDIM) {
            __nv_bfloat16* st = sm + (s ^ 1) * STG;
            size_t ao = abase + k0 + 32, bo = bbase + k0 + 32;
            cpa16(st + soff,              Aghi + ao);
            cpa16(st + soff + 8,          Aghi + ao + 8);
            cpa16(st + ARR + soff,        Aglo + ao);
            cpa16(st + ARR + soff + 8,    Aglo + ao + 8);
            cpa16(st + 2*ARR + soff,      Bghi + bo);
            cpa16(st + 2*ARR + soff + 8,  Bghi + bo + 8);
            cpa16(st + 3*ARR + soff,      Bglo + bo);
            cpa16(st + 3*ARR + soff + 8,  Bglo + bo + 8);
            CP_COMMIT;
        }
        const __nv_bfloat16* Ah = sm + s * STG;
        const __nv_bfloat16* Al = Ah + ARR;
        const __nv_bfloat16* Bh = Ah + 2 * ARR;
        const __nv_bfloat16* Bl = Ah + 3 * ARR;
#pragma unroll
        for (int ks = 0; ks < 32; ks += 16) {
            unsigned afh[4][4], afl[4][4];
#pragma unroll
            for (int mt = 0; mt < 4; mt++) {
                ldsm4(afh[mt], sm32(Ah + (arow + mt * 16) * 40 + ks + acol));
                ldsm4(afl[mt], sm32(Al + (arow + mt * 16) * 40 + ks + acol));
            }
#pragma unroll
            for (int p = 0; p < 2; p++) {
                unsigned bh4[4], bl4[4];
                ldsm4(bh4, sm32(Bh + (wn + p * 16 + bro) * 40 + ks + bco));
                ldsm4(bl4, sm32(Bl + (wn + p * 16 + bro) * 40 + ks + bco));
#pragma unroll
                for (int q = 0; q < 2; q++) {
                    int nt = p * 2 + q;
                    unsigned bfh[2] = {bh4[2 * q], bh4[2 * q + 1]};
                    unsigned bfl[2] = {bl4[2 * q], bl4[2 * q + 1]};
#pragma unroll
                    for (int mt = 0; mt < 4; mt++) {
                        mma_bf16(acc[mt][nt], afh[mt], bfh);
                        mma_bf16(acc[mt][nt], afh[mt], bfl);
                        mma_bf16(acc[mt][nt], afl[mt], bfh);
                    }
                }
            }
        }
        __syncthreads();
    }
}

// =============================================================================
// Kernel A: PW = P @ Wt^T
// =============================================================================
__global__ __launch_bounds__(256, 2) void k_pw_mma() {
    extern __shared__ __align__(16) __nv_bfloat16 sm[];
    const int bm = blockIdx.y * 128, bn = blockIdx.x * 128;
    const int tid = threadIdx.x, warp = tid >> 5, lane = tid & 31;
    const int wm = (warp >> 2) * 64, wn = (warp & 3) * 32;
    const int gid = lane >> 2, tig = lane & 3;
    const int lrow = tid >> 1, lseg = (tid & 1) * 16;

    float acc[4][4][4];
#pragma unroll
    for (int mt = 0; mt < 4; mt++)
#pragma unroll
        for (int nt = 0; nt < 4; nt++)
#pragma unroll
            for (int e = 0; e < 4; e++) acc[mt][nt][e] = 0.0f;

    gemm_nt_body<DH>(sm, g_Phi, g_Plo, g_Wthi, g_Wtlo,
                     (size_t)(bm + lrow) * DH + lseg,
                     (size_t)(bn + lrow) * DH + lseg,
                     acc, wm, wn, lane);

#pragma unroll
    for (int mt = 0; mt < 4; mt++) {
        int r0 = bm + wm + mt * 16 + gid, r1 = r0 + 8;
#pragma unroll
        for (int nt = 0; nt < 4; nt++) {
            int c = bn + wn + nt * 8 + tig * 2;
            float* d = acc[mt][nt];
            BF2 h0, l0, h1, l1;
            split_bf16(d[0], h0.h[0], l0.h[0]);
            split_bf16(d[1], h0.h[1], l0.h[1]);
            split_bf16(d[2], h1.h[0], l1.h[0]);
            split_bf16(d[3], h1.h[1], l1.h[1]);
            *(unsigned*)&g_PWhi[(size_t)r0 * DH + c] = h0.u;
            *(unsigned*)&g_PWlo[(size_t)r0 * DH + c] = l0.u;
            *(unsigned*)&g_PWhi[(size_t)r1 * DH + c] = h1.u;
            *(unsigned*)&g_PWlo[(size_t)r1 * DH + c] = l1.u;
        }
    }
}

// =============================================================================
// Kernel B: sim[b] = PW[b] @ H[b]^T + bias + mask
// =============================================================================
__global__ __launch_bounds__(256, 2) void k_sim(const int* __restrict__ pmask,
                                                const int* __restrict__ hmask,
                                                const float* __restrict__ bias) {
    extern __shared__ __align__(16) __nv_bfloat16 sm[];
    const int b = blockIdx.z;
    const int bm = blockIdx.y * 128, bn = blockIdx.x * 128;
    const int tid = threadIdx.x, warp = tid >> 5, lane = tid & 31;
    const int wm = (warp >> 2) * 64, wn = (warp & 3) * 32;
    const int gid = lane >> 2, tig = lane & 3;
    const int lrow = tid >> 1, lseg = (tid & 1) * 16;

    float acc[4][4][4];
#pragma unroll
    for (int mt = 0; mt < 4; mt++)
#pragma unroll
        for (int nt = 0; nt < 4; nt++)
#pragma unroll
            for (int e = 0; e < 4; e++) acc[mt][nt][e] = 0.0f;

    gemm_nt_body<DH>(sm, g_PWhi, g_PWlo, g_Hhi, g_Hlo,
                     ((size_t)b * LL + bm + lrow) * DH + lseg,
                     ((size_t)b * LL + bn + lrow) * DH + lseg,
                     acc, wm, wn, lane);

    const float bb = bias[0];
#pragma unroll
    for (int mt = 0; mt < 4; mt++) {
        int r0 = bm + wm + mt * 16 + gid, r1 = r0 + 8;
        float pm0 = (float)pmask[b * LL + r0];
        float pm1 = (float)pmask[b * LL + r1];
#pragma unroll
        for (int nt = 0; nt < 4; nt++) {
            int c = bn + wn + nt * 8 + tig * 2;
            float hm0 = (float)hmask[b * LL + c];
            float hm1 = (float)hmask[b * LL + c + 1];
            float* d = acc[mt][nt];
            float2 v0 = make_float2(d[0] + bb + (1.0f - pm0 * hm0) * NEGINF,
                                    d[1] + bb + (1.0f - pm0 * hm1) * NEGINF);
            float2 v1 = make_float2(d[2] + bb + (1.0f - pm1 * hm0) * NEGINF,
                                    d[3] + bb + (1.0f - pm1 * hm1) * NEGINF);
            *(float2*)&g_sim[((size_t)b * LL + r0) * LL + c] = v0;
            *(float2*)&g_sim[((size_t)b * LL + r1) * LL + c] = v1;
        }
    }
}

// =============================================================================
// Kernel C (fused): rowmax/rowinv + colmax partials in ONE pass over sim
// =============================================================================
__global__ __launch_bounds__(256) void k_stats() {
    const int blk = blockIdx.x;                    // 0..127
    const int warp = threadIdx.x >> 5, lane = threadIdx.x & 31;
    const int rowbase = blk * 128 + warp * 16;
    const int b = blk >> 3;

    float4 cm[8];
#pragma unroll
    for (int s = 0; s < 8; s++) cm[s] = make_float4(FLT_LOW, FLT_LOW, FLT_LOW, FLT_LOW);

    for (int r = 0; r < 16; r++) {
        const int row = rowbase + r;
        const float* s = g_sim + (size_t)row * LL + lane * 4;
        float4 v[8];
#pragma unroll
        for (int sg = 0; sg < 8; sg++) v[sg] = *(const float4*)(s + sg * 128);
        float m = FLT_LOW;
#pragma unroll
        for (int sg = 0; sg < 8; sg++) {
            m = fmaxf(m, fmaxf(fmaxf(v[sg].x, v[sg].y), fmaxf(v[sg].z, v[sg].w)));
            cm[sg].x = fmaxf(cm[sg].x, v[sg].x);
            cm[sg].y = fmaxf(cm[sg].y, v[sg].y);
            cm[sg].z = fmaxf(cm[sg].z, v[sg].z);
            cm[sg].w = fmaxf(cm[sg].w, v[sg].w);
        }
#pragma unroll
        for (int o = 16; o > 0; o >>= 1) m = fmaxf(m, __shfl_xor_sync(0xffffffffu, m, o));
        float sum = 0.0f;
#pragma unroll
        for (int sg = 0; sg < 8; sg++)
            sum += __expf(v[sg].x - m) + __expf(v[sg].y - m)
                 + __expf(v[sg].z - m) + __expf(v[sg].w - m);
#pragma unroll
        for (int o = 16; o > 0; o >>= 1) sum += __shfl_xor_sync(0xffffffffu, sum, o);
        if (lane == 0) {
            g_rowmax[row] = m;
            g_rowinv[row] = 1.0f / sum;
        }
    }
    const int chunk = (blk & 7) * 8 + warp;        // 0..63 within batch
    float* cp = g_colpart + ((size_t)b * 64 + chunk) * LL + lane * 4;
#pragma unroll
    for (int sg = 0; sg < 8; sg++) *(float4*)(cp + sg * 128) = cm[sg];
}

// =============================================================================
// Kernel D: aligned_hyp[b] = softmax(sim[b]) @ H[b]
// cp.async double-buffered: raw sim floats + H tiles; exp/split from smem.
// Dyn smem layout (halfwords): Ah[0..5120) Al[5120..10240)
//   Bhs/Bls stages at 10240 + s*8704 (+4352 for Bls)
//   Sraw floats at halfword 27648, stage stride 128*36 floats
// =============================================================================
#define AV_AH 0
#define AV_AL 5120
#define AV_B(s) (10240 + (s) * 8704)
#define AV_SRAW_H 27648
#define AV_SMEM_BYTES (55296 + 2 * 128 * 36 * 4)

__global__ __launch_bounds__(256, 2) void k_av(float* __restrict__ out) {
    extern __shared__ __align__(16) __nv_bfloat16 sm[];
    float* Sraw = (float*)(sm + AV_SRAW_H);
    const int b = blockIdx.z;
    const int bm = blockIdx.y * 128, bn = blockIdx.x * 128;   // bn over DH
    const int tid = threadIdx.x, warp = tid >> 5, lane = tid & 31;
    const int wm = (warp >> 2) * 64, wn = (warp & 3) * 32;
    const int gid = lane >> 2, tig = lane & 3;
    const int lrow = tid >> 1, lseg = (tid & 1) * 16;
    const int arow = wm + (lane & 15), acol = (lane >> 4) * 8;
    const int tkr = (lane & 7) + ((lane >> 3) & 1) * 8;
    const int tdc = ((lane >> 4) & 1) * 8;
    const int qr = tid >> 3, dc = (tid & 7) * 16;

    const float rm = g_rowmax[b * LL + bm + lrow];
    const float ri = g_rowinv[b * LL + bm + lrow];
    const float* sp = &g_sim[((size_t)b * LL + bm + lrow) * LL + lseg];

    float acc[4][4][4];
#pragma unroll
    for (int mt = 0; mt < 4; mt++)
#pragma unroll
        for (int nt = 0; nt < 4; nt++)
#pragma unroll
            for (int e = 0; e < 4; e++) acc[mt][nt][e] = 0.0f;

    // prefetch k0 = 0 (stage 0)
    {
        float* sr = Sraw + lrow * 36 + lseg;
        cpa16(sr,      sp);
        cpa16(sr + 4,  sp + 4);
        cpa16(sr + 8,  sp + 8);
        cpa16(sr + 12, sp + 12);
        size_t hb = ((size_t)b * LL + qr) * DH + bn + dc;
        __nv_bfloat16* bh = sm + AV_B(0) + qr * 136 + dc;
        cpa16(bh,            &g_Hhi[hb]);
        cpa16(bh + 8,        &g_Hhi[hb + 8]);
        cpa16(bh + 4352,     &g_Hlo[hb]);
        cpa16(bh + 4352 + 8, &g_Hlo[hb + 8]);
        CP_COMMIT;
    }
    int s = 0;
    for (int k0 = 0; k0 < LL; k0 += 32, s ^= 1) {
        CP_WAIT0;
        __syncthreads();
        if (k0 + 32 < LL) {
            float* sr = Sraw + (s ^ 1) * 128 * 36 + lrow * 36 + lseg;
            const float* spn = sp + k0 + 32;
            cpa16(sr,      spn);
            cpa16(sr + 4,  spn + 4);
            cpa16(sr + 8,  spn + 8);
            cpa16(sr + 12, spn + 12);
            size_t hb = ((size_t)b * LL + k0 + 32 + qr) * DH + bn + dc;
            __nv_bfloat16* bh = sm + AV_B(s ^ 1) + qr * 136 + dc;
            cpa16(bh,            &g_Hhi[hb]);
            cpa16(bh + 8,        &g_Hhi[hb + 8]);
            cpa16(bh + 4352,     &g_Hlo[hb]);
            cpa16(bh + 4352 + 8, &g_Hlo[hb + 8]);
            CP_COMMIT;
        }
        // exp/split from staged raw sim
        {
            const float* sr = Sraw + s * 128 * 36 + lrow * 36 + lseg;
            BF8 phi0, phi1, plo0, plo1;
#pragma unroll
            for (int i = 0; i < 8; i++) {
                float p0 = __expf(sr[i] - rm) * ri;
                float p1 = __expf(sr[8 + i] - rm) * ri;
                split_bf16(p0, phi0.h[i], plo0.h[i]);
                split_bf16(p1, phi1.h[i], plo1.h[i]);
            }
            *(uint4*)(sm + AV_AH + lrow * 40 + lseg)     = phi0.v;
            *(uint4*)(sm + AV_AH + lrow * 40 + lseg + 8) = phi1.v;
            *(uint4*)(sm + AV_AL + lrow * 40 + lseg)     = plo0.v;
            *(uint4*)(sm + AV_AL + lrow * 40 + lseg + 8) = plo1.v;
        }
        __syncthreads();
        const __nv_bfloat16* Bhs = sm + AV_B(s);
        const __nv_bfloat16* Bls = Bhs + 4352;
#pragma unroll
        for (int ks = 0; ks < 32; ks += 16) {
            unsigned afh[4][4], afl[4][4];
#pragma unroll
            for (int mt = 0; mt < 4; mt++) {
                ldsm4(afh[mt], sm32(sm + AV_AH + (arow + mt * 16) * 40 + ks + acol));
                ldsm4(afl[mt], sm32(sm + AV_AL + (arow + mt * 16) * 40 + ks + acol));
            }
#pragma unroll
            for (int p = 0; p < 2; p++) {
                unsigned bh4[4], bl4[4];
                ldsm4t(bh4, sm32(Bhs + (ks + tkr) * 136 + wn + p * 16 + tdc));
                ldsm4t(bl4, sm32(Bls + (ks + tkr) * 136 + wn + p * 16 + tdc));
#pragma unroll
                for (int q = 0; q < 2; q++) {
                    int nt = p * 2 + q;
                    unsigned bfh[2] = {bh4[2 * q], bh4[2 * q + 1]};
                    unsigned bfl[2] = {bl4[2 * q], bl4[2 * q + 1]};
#pragma unroll
                    for (int mt = 0; mt < 4; mt++) {
                        mma_bf16(acc[mt][nt], afh[mt], bfh);
                        mma_bf16(acc[mt][nt], afh[mt], bfl);
                        mma_bf16(acc[mt][nt], afl[mt], bfh);
                    }
                }
            }
        }
    }
#pragma unroll
    for (int mt = 0; mt < 4; mt++) {
        int r0 = bm + wm + mt * 16 + gid, r1 = r0 + 8;
#pragma unroll
        for (int nt = 0; nt < 4; nt++) {
            int c = bn + wn + nt * 8 + tig * 2;
            float* d = acc[mt][nt];
            *(float2*)&out[((size_t)b * LL + r0) * DH + c] = make_float2(d[0], d[1]);
            *(float2*)&out[((size_t)b * LL + r1) * DH + c] = make_float2(d[2], d[3]);
        }
    }
}

// =============================================================================
// Kernel E: per batch — softmax(colmax over 64 partials) @ P -> g_pvec
// =============================================================================
__global__ __launch_bounds__(256) void k_premise(const float* __restrict__ P) {
    const int b = blockIdx.x;
    const int t = threadIdx.x;
    __shared__ float prob[LL];
    __shared__ float red[8];
    float loc[4];
#pragma unroll
    for (int c = 0; c < 4; c++) {
        int q = c * 256 + t;
        float m = FLT_LOW;
        for (int j = 0; j < 64; j++)
            m = fmaxf(m, g_colpart[((size_t)b * 64 + j) * LL + q]);
        loc[c] = m;
    }
    float mx = fmaxf(fmaxf(loc[0], loc[1]), fmaxf(loc[2], loc[3]));
#pragma unroll
    for (int o = 16; o > 0; o >>= 1) mx = fmaxf(mx, __shfl_xor_sync(0xffffffffu, mx, o));
    const int w = t >> 5, lane = t & 31;
    if (lane == 0) red[w] = mx;
    __syncthreads();
    mx = red[0];
#pragma unroll
    for (int j = 1; j < 8; j++) mx = fmaxf(mx, red[j]);

    float se = 0.0f;
#pragma unroll
    for (int c = 0; c < 4; c++) {
        float e = __expf(loc[c] - mx);
        prob[c * 256 + t] = e;
        se += e;
    }
#pragma unroll
    for (int o = 16; o > 0; o >>= 1) se += __shfl_xor_sync(0xffffffffu, se, o);
    __syncthreads();
    if (lane == 0) red[w] = se;
    __syncthreads();
    float tot = 0.0f;
#pragma unroll
    for (int j = 0; j < 8; j++) tot += red[j];
    const float inv = 1.0f / tot;

    const float* Pb = P + (size_t)b * LL * DH + t;
    float acc = 0.0f;
#pragma unroll 8
    for (int q = 0; q < LL; q++)
        acc = fmaf(prob[q], Pb[(size_t)q * DH], acc);
    g_pvec[b * DH + t] = acc * inv;
}

// =============================================================================
// Kernel F: broadcast g_pvec -> out[0 : NB*LL*DH)
// =============================================================================
__global__ void k_bcast(float* __restrict__ out) {
    int idx = (blockIdx.x * 256 + threadIdx.x) * 4;
    int b = idx >> 18;
    int d = idx & (DH - 1);
    float4 v = *(const float4*)&g_pvec[b * DH + d];
    *(float4*)&out[idx] = v;
}

// =============================================================================
extern "C" void kernel_launch(void* const* d_in, const int* in_sizes, int n_in,
                              void* d_out, int out_size) {
    const float* P    = (const float*)d_in[0];
    const float* Hh   = (const float*)d_in[1];
    const int*   pm   = (const int*)d_in[2];
    const int*   hm   = (const int*)d_in[3];
    const float* W    = (const float*)d_in[4];
    const float* bias = (const float*)d_in[5];
    float* out = (float*)d_out;

    const int gemm_smem = 2 * STG * 2;            // 81920 bytes
    cudaFuncSetAttribute(k_pw_mma, cudaFuncAttributeMaxDynamicSharedMemorySize, gemm_smem);
    cudaFuncSetAttribute(k_sim,    cudaFuncAttributeMaxDynamicSharedMemorySize, gemm_smem);
    cudaFuncSetAttribute(k_av,     cudaFuncAttributeMaxDynamicSharedMemorySize, AV_SMEM_BYTES);

    k_cvtH    <<<(NB * LL * DH) / (256 * 4), 256>>>(Hh);
    k_cvtP    <<<(NB * LL * DH) / (256 * 4), 256>>>(P);
    k_cvtW    <<<DH * DH / 256, 256>>>(W);
    k_pw_mma  <<<dim3(DH / 128, (NB * LL) / 128), 256, gemm_smem>>>();
    k_sim     <<<dim3(LL / 128, LL / 128, NB), 256, gemm_smem>>>(pm, hm, bias);
    k_stats   <<<(NB * LL) / 128, 256>>>();
    k_av      <<<dim3(DH / 128, LL / 128, NB), 256, AV_SMEM_BYTES>>>(out + (size_t)NB * LL * DH);
    k_premise <<<NB, 256>>>(P);
    k_bcast   <<<(NB * LL * DH) / (256 * 4), 256>>>(out);
}

// round 11
// speedup vs baseline: 1.3189x; 1.0607x over previous
#include <cuda_runtime.h>
#include <cuda_bf16.h>

#define NB 16
#define LL 1024
#define DH 256
#define NEGINF (-1e30f)
#define FLT_LOW (-3.4e38f)

// ---------------- scratch (static device globals; no allocation) -------------
__device__ float g_sim[NB * LL * LL];                 // 67 MB scores
__device__ __nv_bfloat16 g_PWhi[NB * LL * DH];
__device__ __nv_bfloat16 g_PWlo[NB * LL * DH];
__device__ __nv_bfloat16 g_Hhi[NB * LL * DH];
__device__ __nv_bfloat16 g_Hlo[NB * LL * DH];
__device__ __nv_bfloat16 g_Phi[NB * LL * DH];
__device__ __nv_bfloat16 g_Plo[NB * LL * DH];
__device__ __nv_bfloat16 g_Wthi[DH * DH];             // W^T split: [e][d]
__device__ __nv_bfloat16 g_Wtlo[DH * DH];
__device__ float g_rowpm[8 * NB * LL];                // per-n-tile row max partials
__device__ float g_rowps[8 * NB * LL];                // per-n-tile row sumexp partials
__device__ float g_rowmax[NB * LL];
__device__ float g_rowinv[NB * LL];
__device__ float g_colpart[NB * 8 * LL];              // 8 p-chunks per batch
__device__ float g_pvec[NB * DH];

union BF8 { uint4 v; __nv_bfloat16 h[8]; };
union BF4 { uint2 v; __nv_bfloat16 h[4]; };
union BF2 { unsigned u; __nv_bfloat16 h[2]; };

__device__ __forceinline__ void mma_bf16(float d[4], const unsigned a[4], const unsigned b[2]) {
    asm volatile(
        "mma.sync.aligned.m16n8k16.row.col.f32.bf16.bf16.f32 "
        "{%0,%1,%2,%3}, {%4,%5,%6,%7}, {%8,%9}, {%0,%1,%2,%3};"
        : "+f"(d[0]), "+f"(d[1]), "+f"(d[2]), "+f"(d[3])
        : "r"(a[0]), "r"(a[1]), "r"(a[2]), "r"(a[3]), "r"(b[0]), "r"(b[1]));
}

__device__ __forceinline__ unsigned sm32(const void* p) {
    return (unsigned)__cvta_generic_to_shared(p);
}
__device__ __forceinline__ void ldsm4(unsigned* r, unsigned a) {
    asm volatile("ldmatrix.sync.aligned.m8n8.x4.shared.b16 {%0,%1,%2,%3}, [%4];"
                 : "=r"(r[0]), "=r"(r[1]), "=r"(r[2]), "=r"(r[3]) : "r"(a));
}
__device__ __forceinline__ void ldsm4t(unsigned* r, unsigned a) {
    asm volatile("ldmatrix.sync.aligned.m8n8.x4.trans.shared.b16 {%0,%1,%2,%3}, [%4];"
                 : "=r"(r[0]), "=r"(r[1]), "=r"(r[2]), "=r"(r[3]) : "r"(a));
}
__device__ __forceinline__ void cpa16(void* dst, const void* src) {
    asm volatile("cp.async.cg.shared.global [%0], [%1], 16;"
                 :: "r"(sm32(dst)), "l"(src));
}
#define CP_COMMIT asm volatile("cp.async.commit_group;")
#define CP_WAIT0  asm volatile("cp.async.wait_group 0;")

__device__ __forceinline__ void split_bf16(float f, __nv_bfloat16& hi, __nv_bfloat16& lo) {
    hi = __float2bfloat16(f);
    lo = __float2bfloat16(f - __bfloat162float(hi));
}

// =============================================================================
// Kernels CVT
// =============================================================================
__global__ void k_cvtH(const float* __restrict__ X) {
    size_t i = ((size_t)blockIdx.x * 256 + threadIdx.x) * 4;
    float4 v = *(const float4*)(X + i);
    BF4 hi, lo;
    split_bf16(v.x, hi.h[0], lo.h[0]);
    split_bf16(v.y, hi.h[1], lo.h[1]);
    split_bf16(v.z, hi.h[2], lo.h[2]);
    split_bf16(v.w, hi.h[3], lo.h[3]);
    *(uint2*)&g_Hhi[i] = hi.v;
    *(uint2*)&g_Hlo[i] = lo.v;
}
__global__ void k_cvtP(const float* __restrict__ X) {
    size_t i = ((size_t)blockIdx.x * 256 + threadIdx.x) * 4;
    float4 v = *(const float4*)(X + i);
    BF4 hi, lo;
    split_bf16(v.x, hi.h[0], lo.h[0]);
    split_bf16(v.y, hi.h[1], lo.h[1]);
    split_bf16(v.z, hi.h[2], lo.h[2]);
    split_bf16(v.w, hi.h[3], lo.h[3]);
    *(uint2*)&g_Phi[i] = hi.v;
    *(uint2*)&g_Plo[i] = lo.v;
}
__global__ void k_cvtW(const float* __restrict__ W) {
    int idx = blockIdx.x * 256 + threadIdx.x;     // 65536
    int d = idx >> 8, e = idx & 255;
    float v = W[idx];
    __nv_bfloat16 hi, lo;
    split_bf16(v, hi, lo);
    g_Wthi[e * DH + d] = hi;
    g_Wtlo[e * DH + d] = lo;
}

// =============================================================================
// Shared GEMM body (NT, split-bf16 3-product, cp.async double-buffer, ldmatrix)
// =============================================================================
#define STG (4 * 128 * 40)        // halfwords per stage
#define ARR (128 * 40)

template<int KDIM>
__device__ __forceinline__ void gemm_nt_body(
    __nv_bfloat16* sm,
    const __nv_bfloat16* __restrict__ Aghi, const __nv_bfloat16* __restrict__ Aglo,
    const __nv_bfloat16* __restrict__ Bghi, const __nv_bfloat16* __restrict__ Bglo,
    size_t abase, size_t bbase, float acc[4][4][4],
    int wm, int wn, int lane)
{
    const int tid = threadIdx.x;
    const int lrow = tid >> 1, lseg = (tid & 1) * 16;
    const int arow = wm + (lane & 15), acol = (lane >> 4) * 8;
    const int bro  = (lane & 7) + ((lane >> 4) & 1) * 8;
    const int bco  = ((lane >> 3) & 1) * 8;
    const int soff = lrow * 40 + lseg;

    {
        __nv_bfloat16* st = sm;
        cpa16(st + soff,              Aghi + abase);
        cpa16(st + soff + 8,          Aghi + abase + 8);
        cpa16(st + ARR + soff,        Aglo + abase);
        cpa16(st + ARR + soff + 8,    Aglo + abase + 8);
        cpa16(st + 2*ARR + soff,      Bghi + bbase);
        cpa16(st + 2*ARR + soff + 8,  Bghi + bbase + 8);
        cpa16(st + 3*ARR + soff,      Bglo + bbase);
        cpa16(st + 3*ARR + soff + 8,  Bglo + bbase + 8);
        CP_COMMIT;
    }
    int s = 0;
    for (int k0 = 0; k0 < KDIM; k0 += 32, s ^= 1) {
        CP_WAIT0;
        __syncthreads();
        if (k0 + 32 < KDIM) {
            __nv_bfloat16* st = sm + (s ^ 1) * STG;
            size_t ao = abase + k0 + 32, bo = bbase + k0 + 32;
            cpa16(st + soff,              Aghi + ao);
            cpa16(st + soff + 8,          Aghi + ao + 8);
            cpa16(st + ARR + soff,        Aglo + ao);
            cpa16(st + ARR + soff + 8,    Aglo + ao + 8);
            cpa16(st + 2*ARR + soff,      Bghi + bo);
            cpa16(st + 2*ARR + soff + 8,  Bghi + bo + 8);
            cpa16(st + 3*ARR + soff,      Bglo + bo);
            cpa16(st + 3*ARR + soff + 8,  Bglo + bo + 8);
            CP_COMMIT;
        }
        const __nv_bfloat16* Ah = sm + s * STG;
        const __nv_bfloat16* Al = Ah + ARR;
        const __nv_bfloat16* Bh = Ah + 2 * ARR;
        const __nv_bfloat16* Bl = Ah + 3 * ARR;
#pragma unroll
        for (int ks = 0; ks < 32; ks += 16) {
            unsigned afh[4][4], afl[4][4];
#pragma unroll
            for (int mt = 0; mt < 4; mt++) {
                ldsm4(afh[mt], sm32(Ah + (arow + mt * 16) * 40 + ks + acol));
                ldsm4(afl[mt], sm32(Al + (arow + mt * 16) * 40 + ks + acol));
            }
#pragma unroll
            for (int p = 0; p < 2; p++) {
                unsigned bh4[4], bl4[4];
                ldsm4(bh4, sm32(Bh + (wn + p * 16 + bro) * 40 + ks + bco));
                ldsm4(bl4, sm32(Bl + (wn + p * 16 + bro) * 40 + ks + bco));
#pragma unroll
                for (int q = 0; q < 2; q++) {
                    int nt = p * 2 + q;
                    unsigned bfh[2] = {bh4[2 * q], bh4[2 * q + 1]};
                    unsigned bfl[2] = {bl4[2 * q], bl4[2 * q + 1]};
#pragma unroll
                    for (int mt = 0; mt < 4; mt++) {
                        mma_bf16(acc[mt][nt], afh[mt], bfh);
                        mma_bf16(acc[mt][nt], afh[mt], bfl);
                        mma_bf16(acc[mt][nt], afl[mt], bfh);
                    }
                }
            }
        }
        __syncthreads();
    }
}

// =============================================================================
// Kernel A: PW = P @ Wt^T
// =============================================================================
__global__ __launch_bounds__(256, 2) void k_pw_mma() {
    extern __shared__ __align__(16) __nv_bfloat16 sm[];
    const int bm = blockIdx.y * 128, bn = blockIdx.x * 128;
    const int tid = threadIdx.x, warp = tid >> 5, lane = tid & 31;
    const int wm = (warp >> 2) * 64, wn = (warp & 3) * 32;
    const int gid = lane >> 2, tig = lane & 3;
    const int lrow = tid >> 1, lseg = (tid & 1) * 16;

    float acc[4][4][4];
#pragma unroll
    for (int mt = 0; mt < 4; mt++)
#pragma unroll
        for (int nt = 0; nt < 4; nt++)
#pragma unroll
            for (int e = 0; e < 4; e++) acc[mt][nt][e] = 0.0f;

    gemm_nt_body<DH>(sm, g_Phi, g_Plo, g_Wthi, g_Wtlo,
                     (size_t)(bm + lrow) * DH + lseg,
                     (size_t)(bn + lrow) * DH + lseg,
                     acc, wm, wn, lane);

#pragma unroll
    for (int mt = 0; mt < 4; mt++) {
        int r0 = bm + wm + mt * 16 + gid, r1 = r0 + 8;
#pragma unroll
        for (int nt = 0; nt < 4; nt++) {
            int c = bn + wn + nt * 8 + tig * 2;
            float* d = acc[mt][nt];
            BF2 h0, l0, h1, l1;
            split_bf16(d[0], h0.h[0], l0.h[0]);
            split_bf16(d[1], h0.h[1], l0.h[1]);
            split_bf16(d[2], h1.h[0], l1.h[0]);
            split_bf16(d[3], h1.h[1], l1.h[1]);
            *(unsigned*)&g_PWhi[(size_t)r0 * DH + c] = h0.u;
            *(unsigned*)&g_PWlo[(size_t)r0 * DH + c] = l0.u;
            *(unsigned*)&g_PWhi[(size_t)r1 * DH + c] = h1.u;
            *(unsigned*)&g_PWlo[(size_t)r1 * DH + c] = l1.u;
        }
    }
}

// =============================================================================
// Kernel B: sim[b] = PW[b] @ H[b]^T + bias + mask, WITH fused stats partials:
//   g_rowpm/g_rowps[bnIdx][b*LL+row]   (row max / sumexp over this 128-col tile)
//   g_colpart[b*8+bmIdx][col]          (col max over this 128-row tile)
// =============================================================================
__global__ __launch_bounds__(256, 2) void k_sim(const int* __restrict__ pmask,
                                                const int* __restrict__ hmask,
                                                const float* __restrict__ bias) {
    extern __shared__ __align__(16) __nv_bfloat16 sm[];
    const int b = blockIdx.z;
    const int bm = blockIdx.y * 128, bn = blockIdx.x * 128;
    const int tid = threadIdx.x, warp = tid >> 5, lane = tid & 31;
    const int wm = (warp >> 2) * 64, wn = (warp & 3) * 32;
    const int gid = lane >> 2, tig = lane & 3;
    const int lrow = tid >> 1, lseg = (tid & 1) * 16;

    float acc[4][4][4];
#pragma unroll
    for (int mt = 0; mt < 4; mt++)
#pragma unroll
        for (int nt = 0; nt < 4; nt++)
#pragma unroll
            for (int e = 0; e < 4; e++) acc[mt][nt][e] = 0.0f;

    gemm_nt_body<DH>(sm, g_PWhi, g_PWlo, g_Hhi, g_Hlo,
                     ((size_t)b * LL + bm + lrow) * DH + lseg,
                     ((size_t)b * LL + bn + lrow) * DH + lseg,
                     acc, wm, wn, lane);

    const float bb = bias[0];
#pragma unroll
    for (int mt = 0; mt < 4; mt++) {
        int r0 = bm + wm + mt * 16 + gid, r1 = r0 + 8;
        float pm0 = (float)pmask[b * LL + r0];
        float pm1 = (float)pmask[b * LL + r1];
#pragma unroll
        for (int nt = 0; nt < 4; nt++) {
            int c = bn + wn + nt * 8 + tig * 2;
            float hm0 = (float)hmask[b * LL + c];
            float hm1 = (float)hmask[b * LL + c + 1];
            float* d = acc[mt][nt];
            d[0] += bb + (1.0f - pm0 * hm0) * NEGINF;
            d[1] += bb + (1.0f - pm0 * hm1) * NEGINF;
            d[2] += bb + (1.0f - pm1 * hm0) * NEGINF;
            d[3] += bb + (1.0f - pm1 * hm1) * NEGINF;
            *(float2*)&g_sim[((size_t)b * LL + r0) * LL + c] = make_float2(d[0], d[1]);
            *(float2*)&g_sim[((size_t)b * LL + r1) * LL + c] = make_float2(d[2], d[3]);
        }
    }

    // ---- fused stats partials (reuse smem as float scratch) ----
    float* S = (float*)sm;
    float* rowmS = S;            // [4][128] per wn-group row maxes
    float* rowsS = S + 512;      // [4][128] per wn-group row sumexp
    float* colmS = S + 1024;     // [2][128] per wm-group col maxes
    const int wng = warp & 3, wrow = warp >> 2;
    __syncthreads();             // done reading GEMM smem

    // per-warp row maxes over its 32 cols
#pragma unroll
    for (int mt = 0; mt < 4; mt++) {
        float m0 = FLT_LOW, m1 = FLT_LOW;
#pragma unroll
        for (int nt = 0; nt < 4; nt++) {
            m0 = fmaxf(m0, fmaxf(acc[mt][nt][0], acc[mt][nt][1]));
            m1 = fmaxf(m1, fmaxf(acc[mt][nt][2], acc[mt][nt][3]));
        }
        m0 = fmaxf(m0, __shfl_xor_sync(0xffffffffu, m0, 1));
        m0 = fmaxf(m0, __shfl_xor_sync(0xffffffffu, m0, 2));
        m1 = fmaxf(m1, __shfl_xor_sync(0xffffffffu, m1, 1));
        m1 = fmaxf(m1, __shfl_xor_sync(0xffffffffu, m1, 2));
        if (tig == 0) {
            rowmS[wng * 128 + wm + mt * 16 + gid]     = m0;
            rowmS[wng * 128 + wm + mt * 16 + gid + 8] = m1;
        }
    }
    // per-warp-row col maxes over its 64 rows
#pragma unroll
    for (int nt = 0; nt < 4; nt++) {
        float c0 = FLT_LOW, c1 = FLT_LOW;
#pragma unroll
        for (int mt = 0; mt < 4; mt++) {
            c0 = fmaxf(c0, fmaxf(acc[mt][nt][0], acc[mt][nt][2]));
            c1 = fmaxf(c1, fmaxf(acc[mt][nt][1], acc[mt][nt][3]));
        }
        c0 = fmaxf(c0, __shfl_xor_sync(0xffffffffu, c0, 4));
        c0 = fmaxf(c0, __shfl_xor_sync(0xffffffffu, c0, 8));
        c0 = fmaxf(c0, __shfl_xor_sync(0xffffffffu, c0, 16));
        c1 = fmaxf(c1, __shfl_xor_sync(0xffffffffu, c1, 4));
        c1 = fmaxf(c1, __shfl_xor_sync(0xffffffffu, c1, 8));
        c1 = fmaxf(c1, __shfl_xor_sync(0xffffffffu, c1, 16));
        if (gid == 0) {
            colmS[wrow * 128 + wn + nt * 8 + tig * 2]     = c0;
            colmS[wrow * 128 + wn + nt * 8 + tig * 2 + 1] = c1;
        }
    }
    __syncthreads();

    // sumexp vs tile row max
#pragma unroll
    for (int mt = 0; mt < 4; mt++) {
        int lr0 = wm + mt * 16 + gid, lr1 = lr0 + 8;
        float m0 = fmaxf(fmaxf(rowmS[lr0], rowmS[128 + lr0]),
                         fmaxf(rowmS[256 + lr0], rowmS[384 + lr0]));
        float m1 = fmaxf(fmaxf(rowmS[lr1], rowmS[128 + lr1]),
                         fmaxf(rowmS[256 + lr1], rowmS[384 + lr1]));
        float s0 = 0.0f, s1 = 0.0f;
#pragma unroll
        for (int nt = 0; nt < 4; nt++) {
            s0 += __expf(acc[mt][nt][0] - m0) + __expf(acc[mt][nt][1] - m0);
            s1 += __expf(acc[mt][nt][2] - m1) + __expf(acc[mt][nt][3] - m1);
        }
        s0 += __shfl_xor_sync(0xffffffffu, s0, 1);
        s0 += __shfl_xor_sync(0xffffffffu, s0, 2);
        s1 += __shfl_xor_sync(0xffffffffu, s1, 1);
        s1 += __shfl_xor_sync(0xffffffffu, s1, 2);
        if (tig == 0) {
            rowsS[wng * 128 + lr0] = s0;
            rowsS[wng * 128 + lr1] = s1;
        }
    }
    __syncthreads();

    if (tid < 128) {
        float m = fmaxf(fmaxf(rowmS[tid], rowmS[128 + tid]),
                        fmaxf(rowmS[256 + tid], rowmS[384 + tid]));
        float s = rowsS[tid] + rowsS[128 + tid] + rowsS[256 + tid] + rowsS[384 + tid];
        size_t ro = (size_t)blockIdx.x * (NB * LL) + (size_t)b * LL + bm + tid;
        g_rowpm[ro] = m;
        g_rowps[ro] = s;
        float cm = fmaxf(colmS[tid], colmS[128 + tid]);
        g_colpart[((size_t)b * 8 + blockIdx.y) * LL + bn + tid] = cm;
    }
}

// =============================================================================
// Kernel C2: combine 8 row partials -> rowmax / rowinv
// =============================================================================
__global__ void k_finstats() {
    int row = blockIdx.x * 256 + threadIdx.x;     // < NB*LL
    float mj[8];
    float m = FLT_LOW;
#pragma unroll
    for (int j = 0; j < 8; j++) {
        mj[j] = g_rowpm[j * (NB * LL) + row];
        m = fmaxf(m, mj[j]);
    }
    float s = 0.0f;
#pragma unroll
    for (int j = 0; j < 8; j++)
        s += g_rowps[j * (NB * LL) + row] * __expf(mj[j] - m);
    g_rowmax[row] = m;
    g_rowinv[row] = 1.0f / s;
}

// =============================================================================
// Kernel D: aligned_hyp[b] = softmax(sim[b]) @ H[b]  (cp.async, ldmatrix.trans)
// =============================================================================
#define AV_AH 0
#define AV_AL 5120
#define AV_B(s) (10240 + (s) * 8704)
#define AV_SRAW_H 27648
#define AV_SMEM_BYTES (55296 + 2 * 128 * 36 * 4)

__global__ __launch_bounds__(256, 2) void k_av(float* __restrict__ out) {
    extern __shared__ __align__(16) __nv_bfloat16 sm[];
    float* Sraw = (float*)(sm + AV_SRAW_H);
    const int b = blockIdx.z;
    const int bm = blockIdx.y * 128, bn = blockIdx.x * 128;   // bn over DH
    const int tid = threadIdx.x, warp = tid >> 5, lane = tid & 31;
    const int wm = (warp >> 2) * 64, wn = (warp & 3) * 32;
    const int gid = lane >> 2, tig = lane & 3;
    const int lrow = tid >> 1, lseg = (tid & 1) * 16;
    const int arow = wm + (lane & 15), acol = (lane >> 4) * 8;
    const int tkr = (lane & 7) + ((lane >> 3) & 1) * 8;
    const int tdc = ((lane >> 4) & 1) * 8;
    const int qr = tid >> 3, dc = (tid & 7) * 16;

    const float rm = g_rowmax[b * LL + bm + lrow];
    const float ri = g_rowinv[b * LL + bm + lrow];
    const float* sp = &g_sim[((size_t)b * LL + bm + lrow) * LL + lseg];

    float acc[4][4][4];
#pragma unroll
    for (int mt = 0; mt < 4; mt++)
#pragma unroll
        for (int nt = 0; nt < 4; nt++)
#pragma unroll
            for (int e = 0; e < 4; e++) acc[mt][nt][e] = 0.0f;

    {
        float* sr = Sraw + lrow * 36 + lseg;
        cpa16(sr,      sp);
        cpa16(sr + 4,  sp + 4);
        cpa16(sr + 8,  sp + 8);
        cpa16(sr + 12, sp + 12);
        size_t hb = ((size_t)b * LL + qr) * DH + bn + dc;
        __nv_bfloat16* bh = sm + AV_B(0) + qr * 136 + dc;
        cpa16(bh,            &g_Hhi[hb]);
        cpa16(bh + 8,        &g_Hhi[hb + 8]);
        cpa16(bh + 4352,     &g_Hlo[hb]);
        cpa16(bh + 4352 + 8, &g_Hlo[hb + 8]);
        CP_COMMIT;
    }
    int s = 0;
    for (int k0 = 0; k0 < LL; k0 += 32, s ^= 1) {
        CP_WAIT0;
        __syncthreads();
        if (k0 + 32 < LL) {
            float* sr = Sraw + (s ^ 1) * 128 * 36 + lrow * 36 + lseg;
            const float* spn = sp + k0 + 32;
            cpa16(sr,      spn);
            cpa16(sr + 4,  spn + 4);
            cpa16(sr + 8,  spn + 8);
            cpa16(sr + 12, spn + 12);
            size_t hb = ((size_t)b * LL + k0 + 32 + qr) * DH + bn + dc;
            __nv_bfloat16* bh = sm + AV_B(s ^ 1) + qr * 136 + dc;
            cpa16(bh,            &g_Hhi[hb]);
            cpa16(bh + 8,        &g_Hhi[hb + 8]);
            cpa16(bh + 4352,     &g_Hlo[hb]);
            cpa16(bh + 4352 + 8, &g_Hlo[hb + 8]);
            CP_COMMIT;
        }
        {
            const float* sr = Sraw + s * 128 * 36 + lrow * 36 + lseg;
            BF8 phi0, phi1, plo0, plo1;
#pragma unroll
            for (int i = 0; i < 8; i++) {
                float p0 = __expf(sr[i] - rm) * ri;
                float p1 = __expf(sr[8 + i] - rm) * ri;
                split_bf16(p0, phi0.h[i], plo0.h[i]);
                split_bf16(p1, phi1.h[i], plo1.h[i]);
            }
            *(uint4*)(sm + AV_AH + lrow * 40 + lseg)     = phi0.v;
            *(uint4*)(sm + AV_AH + lrow * 40 + lseg + 8) = phi1.v;
            *(uint4*)(sm + AV_AL + lrow * 40 + lseg)     = plo0.v;
            *(uint4*)(sm + AV_AL + lrow * 40 + lseg + 8) = plo1.v;
        }
        __syncthreads();
        const __nv_bfloat16* Bhs = sm + AV_B(s);
        const __nv_bfloat16* Bls = Bhs + 4352;
#pragma unroll
        for (int ks = 0; ks < 32; ks += 16) {
            unsigned afh[4][4], afl[4][4];
#pragma unroll
            for (int mt = 0; mt < 4; mt++) {
                ldsm4(afh[mt], sm32(sm + AV_AH + (arow + mt * 16) * 40 + ks + acol));
                ldsm4(afl[mt], sm32(sm + AV_AL + (arow + mt * 16) * 40 + ks + acol));
            }
#pragma unroll
            for (int p = 0; p < 2; p++) {
                unsigned bh4[4], bl4[4];
                ldsm4t(bh4, sm32(Bhs + (ks + tkr) * 136 + wn + p * 16 + tdc));
                ldsm4t(bl4, sm32(Bls + (ks + tkr) * 136 + wn + p * 16 + tdc));
#pragma unroll
                for (int q = 0; q < 2; q++) {
                    int nt = p * 2 + q;
                    unsigned bfh[2] = {bh4[2 * q], bh4[2 * q + 1]};
                    unsigned bfl[2] = {bl4[2 * q], bl4[2 * q + 1]};
#pragma unroll
                    for (int mt = 0; mt < 4; mt++) {
                        mma_bf16(acc[mt][nt], afh[mt], bfh);
                        mma_bf16(acc[mt][nt], afh[mt], bfl);
                        mma_bf16(acc[mt][nt], afl[mt], bfh);
                    }
                }
            }
        }
    }
#pragma unroll
    for (int mt = 0; mt < 4; mt++) {
        int r0 = bm + wm + mt * 16 + gid, r1 = r0 + 8;
#pragma unroll
        for (int nt = 0; nt < 4; nt++) {
            int c = bn + wn + nt * 8 + tig * 2;
            float* d = acc[mt][nt];
            *(float2*)&out[((size_t)b * LL + r0) * DH + c] = make_float2(d[0], d[1]);
            *(float2*)&out[((size_t)b * LL + r1) * DH + c] = make_float2(d[2], d[3]);
        }
    }
}

// =============================================================================
// Kernel E: per batch — softmax(colmax over 8 partials) @ P -> g_pvec
// =============================================================================
__global__ __launch_bounds__(256) void k_premise(const float* __restrict__ P) {
    const int b = blockIdx.x;
    const int t = threadIdx.x;
    __shared__ float prob[LL];
    __shared__ float red[8];
    float loc[4];
#pragma unroll
    for (int c = 0; c < 4; c++) {
        int q = c * 256 + t;
        float m = FLT_LOW;
#pragma unroll
        for (int j = 0; j < 8; j++)
            m = fmaxf(m, g_colpart[((size_t)b * 8 + j) * LL + q]);
        loc[c] = m;
    }
    float mx = fmaxf(fmaxf(loc[0], loc[1]), fmaxf(loc[2], loc[3]));
#pragma unroll
    for (int o = 16; o > 0; o >>= 1) mx = fmaxf(mx, __shfl_xor_sync(0xffffffffu, mx, o));
    const int w = t >> 5, lane = t & 31;
    if (lane == 0) red[w] = mx;
    __syncthreads();
    mx = red[0];
#pragma unroll
    for (int j = 1; j < 8; j++) mx = fmaxf(mx, red[j]);

    float se = 0.0f;
#pragma unroll
    for (int c = 0; c < 4; c++) {
        float e = __expf(loc[c] - mx);
        prob[c * 256 + t] = e;
        se += e;
    }
#pragma unroll
    for (int o = 16; o > 0; o >>= 1) se += __shfl_xor_sync(0xffffffffu, se, o);
    __syncthreads();
    if (lane == 0) red[w] = se;
    __syncthreads();
    float tot = 0.0f;
#pragma unroll
    for (int j = 0; j < 8; j++) tot += red[j];
    const float inv = 1.0f / tot;

    const float* Pb = P + (size_t)b * LL * DH + t;
    float acc = 0.0f;
#pragma unroll 8
    for (int q = 0; q < LL; q++)
        acc = fmaf(prob[q], Pb[(size_t)q * DH], acc);
    g_pvec[b * DH + t] = acc * inv;
}

// =============================================================================
// Kernel F: broadcast g_pvec -> out[0 : NB*LL*DH)
// =============================================================================
__global__ void k_bcast(float* __restrict__ out) {
    int idx = (blockIdx.x * 256 + threadIdx.x) * 4;
    int b = idx >> 18;
    int d = idx & (DH - 1);
    float4 v = *(const float4*)&g_pvec[b * DH + d];
    *(float4*)&out[idx] = v;
}

// =============================================================================
extern "C" void kernel_launch(void* const* d_in, const int* in_sizes, int n_in,
                              void* d_out, int out_size) {
    const float* P    = (const float*)d_in[0];
    const float* Hh   = (const float*)d_in[1];
    const int*   pm   = (const int*)d_in[2];
    const int*   hm   = (const int*)d_in[3];
    const float* W    = (const float*)d_in[4];
    const float* bias = (const float*)d_in[5];
    float* out = (float*)d_out;

    const int gemm_smem = 2 * STG * 2;            // 81920 bytes
    cudaFuncSetAttribute(k_pw_mma, cudaFuncAttributeMaxDynamicSharedMemorySize, gemm_smem);
    cudaFuncSetAttribute(k_sim,    cudaFuncAttributeMaxDynamicSharedMemorySize, gemm_smem);
    cudaFuncSetAttribute(k_av,     cudaFuncAttributeMaxDynamicSharedMemorySize, AV_SMEM_BYTES);

    k_cvtH     <<<(NB * LL * DH) / (256 * 4), 256>>>(Hh);
    k_cvtP     <<<(NB * LL * DH) / (256 * 4), 256>>>(P);
    k_cvtW     <<<DH * DH / 256, 256>>>(W);
    k_pw_mma   <<<dim3(DH / 128, (NB * LL) / 128), 256, gemm_smem>>>();
    k_sim      <<<dim3(LL / 128, LL / 128, NB), 256, gemm_smem>>>(pm, hm, bias);
    k_finstats <<<(NB * LL) / 256, 256>>>();
    k_av       <<<dim3(DH / 128, LL / 128, NB), 256, AV_SMEM_BYTES>>>(out + (size_t)NB * LL * DH);
    k_premise  <<<NB, 256>>>(P);
    k_bcast    <<<(NB * LL * DH) / (256 * 4), 256>>>(out);
}

// round 12
// speedup vs baseline: 1.3418x; 1.0174x over previous
#include <cuda_runtime.h>
#include <cuda_bf16.h>

#define NB 16
#define LL 1024
#define DH 256
#define NEGINF (-1e30f)
#define FLT_LOW (-3.4e38f)

// ---------------- scratch (static device globals; no allocation) -------------
__device__ float g_sim[NB * LL * LL];                 // 67 MB scores
__device__ __nv_bfloat16 g_PWhi[NB * LL * DH];
__device__ __nv_bfloat16 g_PWlo[NB * LL * DH];
__device__ __nv_bfloat16 g_Hhi[NB * LL * DH];
__device__ __nv_bfloat16 g_Hlo[NB * LL * DH];
__device__ __nv_bfloat16 g_Phi[NB * LL * DH];
__device__ __nv_bfloat16 g_Plo[NB * LL * DH];
__device__ __nv_bfloat16 g_Wthi[DH * DH];             // W^T split: [e][d]
__device__ __nv_bfloat16 g_Wtlo[DH * DH];
__device__ float g_rowpm[8 * NB * LL];                // per-n-tile row max partials
__device__ float g_rowps[8 * NB * LL];                // per-n-tile row sumexp partials
__device__ float g_rowmax[NB * LL];
__device__ float g_rowinv[NB * LL];
__device__ float g_colpart[NB * 8 * LL];              // 8 p-chunks per batch
__device__ float g_pvec[NB * DH];

union BF8 { uint4 v; __nv_bfloat16 h[8]; };
union BF4 { uint2 v; __nv_bfloat16 h[4]; };
union BF2 { unsigned u; __nv_bfloat16 h[2]; };

__device__ __forceinline__ void mma_bf16(float d[4], const unsigned a[4], const unsigned b[2]) {
    asm volatile(
        "mma.sync.aligned.m16n8k16.row.col.f32.bf16.bf16.f32 "
        "{%0,%1,%2,%3}, {%4,%5,%6,%7}, {%8,%9}, {%0,%1,%2,%3};"
        : "+f"(d[0]), "+f"(d[1]), "+f"(d[2]), "+f"(d[3])
        : "r"(a[0]), "r"(a[1]), "r"(a[2]), "r"(a[3]), "r"(b[0]), "r"(b[1]));
}

__device__ __forceinline__ unsigned sm32(const void* p) {
    return (unsigned)__cvta_generic_to_shared(p);
}
__device__ __forceinline__ void ldsm4(unsigned* r, unsigned a) {
    asm volatile("ldmatrix.sync.aligned.m8n8.x4.shared.b16 {%0,%1,%2,%3}, [%4];"
                 : "=r"(r[0]), "=r"(r[1]), "=r"(r[2]), "=r"(r[3]) : "r"(a));
}
__device__ __forceinline__ void ldsm4t(unsigned* r, unsigned a) {
    asm volatile("ldmatrix.sync.aligned.m8n8.x4.trans.shared.b16 {%0,%1,%2,%3}, [%4];"
                 : "=r"(r[0]), "=r"(r[1]), "=r"(r[2]), "=r"(r[3]) : "r"(a));
}
__device__ __forceinline__ void cpa16(void* dst, const void* src) {
    asm volatile("cp.async.cg.shared.global [%0], [%1], 16;"
                 :: "r"(sm32(dst)), "l"(src));
}
#define CP_COMMIT asm volatile("cp.async.commit_group;")
#define CP_WAIT0  asm volatile("cp.async.wait_group 0;")

__device__ __forceinline__ void split_bf16(float f, __nv_bfloat16& hi, __nv_bfloat16& lo) {
    hi = __float2bfloat16(f);
    lo = __float2bfloat16(f - __bfloat162float(hi));
}

// =============================================================================
// Kernels CVT
// =============================================================================
__global__ void k_cvtH(const float* __restrict__ X) {
    size_t i = ((size_t)blockIdx.x * 256 + threadIdx.x) * 4;
    float4 v = *(const float4*)(X + i);
    BF4 hi, lo;
    split_bf16(v.x, hi.h[0], lo.h[0]);
    split_bf16(v.y, hi.h[1], lo.h[1]);
    split_bf16(v.z, hi.h[2], lo.h[2]);
    split_bf16(v.w, hi.h[3], lo.h[3]);
    *(uint2*)&g_Hhi[i] = hi.v;
    *(uint2*)&g_Hlo[i] = lo.v;
}
__global__ void k_cvtP(const float* __restrict__ X) {
    size_t i = ((size_t)blockIdx.x * 256 + threadIdx.x) * 4;
    float4 v = *(const float4*)(X + i);
    BF4 hi, lo;
    split_bf16(v.x, hi.h[0], lo.h[0]);
    split_bf16(v.y, hi.h[1], lo.h[1]);
    split_bf16(v.z, hi.h[2], lo.h[2]);
    split_bf16(v.w, hi.h[3], lo.h[3]);
    *(uint2*)&g_Phi[i] = hi.v;
    *(uint2*)&g_Plo[i] = lo.v;
}
__global__ void k_cvtW(const float* __restrict__ W) {
    int idx = blockIdx.x * 256 + threadIdx.x;     // 65536
    int d = idx >> 8, e = idx & 255;
    float v = W[idx];
    __nv_bfloat16 hi, lo;
    split_bf16(v, hi, lo);
    g_Wthi[e * DH + d] = hi;
    g_Wtlo[e * DH + d] = lo;
}

// =============================================================================
// Shared GEMM body (NT, split-bf16 3-product, cp.async double-buffer, ldmatrix)
// Inner loop PRODUCT-MAJOR: 8 independent MMAs between accumulator reuse.
// =============================================================================
#define STG (4 * 128 * 40)        // halfwords per stage
#define ARR (128 * 40)

template<int KDIM>
__device__ __forceinline__ void gemm_nt_body(
    __nv_bfloat16* sm,
    const __nv_bfloat16* __restrict__ Aghi, const __nv_bfloat16* __restrict__ Aglo,
    const __nv_bfloat16* __restrict__ Bghi, const __nv_bfloat16* __restrict__ Bglo,
    size_t abase, size_t bbase, float acc[4][4][4],
    int wm, int wn, int lane)
{
    const int tid = threadIdx.x;
    const int lrow = tid >> 1, lseg = (tid & 1) * 16;
    const int arow = wm + (lane & 15), acol = (lane >> 4) * 8;
    const int bro  = (lane & 7) + ((lane >> 4) & 1) * 8;
    const int bco  = ((lane >> 3) & 1) * 8;
    const int soff = lrow * 40 + lseg;

    {
        __nv_bfloat16* st = sm;
        cpa16(st + soff,              Aghi + abase);
        cpa16(st + soff + 8,          Aghi + abase + 8);
        cpa16(st + ARR + soff,        Aglo + abase);
        cpa16(st + ARR + soff + 8,    Aglo + abase + 8);
        cpa16(st + 2*ARR + soff,      Bghi + bbase);
        cpa16(st + 2*ARR + soff + 8,  Bghi + bbase + 8);
        cpa16(st + 3*ARR + soff,      Bglo + bbase);
        cpa16(st + 3*ARR + soff + 8,  Bglo + bbase + 8);
        CP_COMMIT;
    }
    int s = 0;
    for (int k0 = 0; k0 < KDIM; k0 += 32, s ^= 1) {
        CP_WAIT0;
        __syncthreads();
        if (k0 + 32 < KDIM) {
            __nv_bfloat16* st = sm + (s ^ 1) * STG;
            size_t ao = abase + k0 + 32, bo = bbase + k0 + 32;
            cpa16(st + soff,              Aghi + ao);
            cpa16(st + soff + 8,          Aghi + ao + 8);
            cpa16(st + ARR + soff,        Aglo + ao);
            cpa16(st + ARR + soff + 8,    Aglo + ao + 8);
            cpa16(st + 2*ARR + soff,      Bghi + bo);
            cpa16(st + 2*ARR + soff + 8,  Bghi + bo + 8);
            cpa16(st + 3*ARR + soff,      Bglo + bo);
            cpa16(st + 3*ARR + soff + 8,  Bglo + bo + 8);
            CP_COMMIT;
        }
        const __nv_bfloat16* Ah = sm + s * STG;
        const __nv_bfloat16* Al = Ah + ARR;
        const __nv_bfloat16* Bh = Ah + 2 * ARR;
        const __nv_bfloat16* Bl = Ah + 3 * ARR;
#pragma unroll
        for (int ks = 0; ks < 32; ks += 16) {
            unsigned afh[4][4], afl[4][4];
#pragma unroll
            for (int mt = 0; mt < 4; mt++) {
                ldsm4(afh[mt], sm32(Ah + (arow + mt * 16) * 40 + ks + acol));
                ldsm4(afl[mt], sm32(Al + (arow + mt * 16) * 40 + ks + acol));
            }
#pragma unroll
            for (int p = 0; p < 2; p++) {
                unsigned bh4[4], bl4[4];
                ldsm4(bh4, sm32(Bh + (wn + p * 16 + bro) * 40 + ks + bco));
                ldsm4(bl4, sm32(Bl + (wn + p * 16 + bro) * 40 + ks + bco));
                // product-major: 8 independent accs per product sweep
#pragma unroll
                for (int mt = 0; mt < 4; mt++)
#pragma unroll
                    for (int q = 0; q < 2; q++)
                        mma_bf16(acc[mt][p * 2 + q], afh[mt], &bh4[2 * q]);
#pragma unroll
                for (int mt = 0; mt < 4; mt++)
#pragma unroll
                    for (int q = 0; q < 2; q++)
                        mma_bf16(acc[mt][p * 2 + q], afh[mt], &bl4[2 * q]);
#pragma unroll
                for (int mt = 0; mt < 4; mt++)
#pragma unroll
                    for (int q = 0; q < 2; q++)
                        mma_bf16(acc[mt][p * 2 + q], afl[mt], &bh4[2 * q]);
            }
        }
        __syncthreads();
    }
}

// =============================================================================
// Kernel A: PW = P @ Wt^T
// =============================================================================
__global__ __launch_bounds__(256, 2) void k_pw_mma() {
    extern __shared__ __align__(16) __nv_bfloat16 sm[];
    const int bm = blockIdx.y * 128, bn = blockIdx.x * 128;
    const int tid = threadIdx.x, warp = tid >> 5, lane = tid & 31;
    const int wm = (warp >> 2) * 64, wn = (warp & 3) * 32;
    const int gid = lane >> 2, tig = lane & 3;
    const int lrow = tid >> 1, lseg = (tid & 1) * 16;

    float acc[4][4][4];
#pragma unroll
    for (int mt = 0; mt < 4; mt++)
#pragma unroll
        for (int nt = 0; nt < 4; nt++)
#pragma unroll
            for (int e = 0; e < 4; e++) acc[mt][nt][e] = 0.0f;

    gemm_nt_body<DH>(sm, g_Phi, g_Plo, g_Wthi, g_Wtlo,
                     (size_t)(bm + lrow) * DH + lseg,
                     (size_t)(bn + lrow) * DH + lseg,
                     acc, wm, wn, lane);

#pragma unroll
    for (int mt = 0; mt < 4; mt++) {
        int r0 = bm + wm + mt * 16 + gid, r1 = r0 + 8;
#pragma unroll
        for (int nt = 0; nt < 4; nt++) {
            int c = bn + wn + nt * 8 + tig * 2;
            float* d = acc[mt][nt];
            BF2 h0, l0, h1, l1;
            split_bf16(d[0], h0.h[0], l0.h[0]);
            split_bf16(d[1], h0.h[1], l0.h[1]);
            split_bf16(d[2], h1.h[0], l1.h[0]);
            split_bf16(d[3], h1.h[1], l1.h[1]);
            *(unsigned*)&g_PWhi[(size_t)r0 * DH + c] = h0.u;
            *(unsigned*)&g_PWlo[(size_t)r0 * DH + c] = l0.u;
            *(unsigned*)&g_PWhi[(size_t)r1 * DH + c] = h1.u;
            *(unsigned*)&g_PWlo[(size_t)r1 * DH + c] = l1.u;
        }
    }
}

// =============================================================================
// Kernel B: sim[b] = PW[b] @ H[b]^T + bias + mask, WITH fused stats partials
// =============================================================================
__global__ __launch_bounds__(256, 2) void k_sim(const int* __restrict__ pmask,
                                                const int* __restrict__ hmask,
                                                const float* __restrict__ bias) {
    extern __shared__ __align__(16) __nv_bfloat16 sm[];
    const int b = blockIdx.z;
    const int bm = blockIdx.y * 128, bn = blockIdx.x * 128;
    const int tid = threadIdx.x, warp = tid >> 5, lane = tid & 31;
    const int wm = (warp >> 2) * 64, wn = (warp & 3) * 32;
    const int gid = lane >> 2, tig = lane & 3;
    const int lrow = tid >> 1, lseg = (tid & 1) * 16;

    float acc[4][4][4];
#pragma unroll
    for (int mt = 0; mt < 4; mt++)
#pragma unroll
        for (int nt = 0; nt < 4; nt++)
#pragma unroll
            for (int e = 0; e < 4; e++) acc[mt][nt][e] = 0.0f;

    gemm_nt_body<DH>(sm, g_PWhi, g_PWlo, g_Hhi, g_Hlo,
                     ((size_t)b * LL + bm + lrow) * DH + lseg,
                     ((size_t)b * LL + bn + lrow) * DH + lseg,
                     acc, wm, wn, lane);

    const float bb = bias[0];
#pragma unroll
    for (int mt = 0; mt < 4; mt++) {
        int r0 = bm + wm + mt * 16 + gid, r1 = r0 + 8;
        float pm0 = (float)pmask[b * LL + r0];
        float pm1 = (float)pmask[b * LL + r1];
#pragma unroll
        for (int nt = 0; nt < 4; nt++) {
            int c = bn + wn + nt * 8 + tig * 2;
            float hm0 = (float)hmask[b * LL + c];
            float hm1 = (float)hmask[b * LL + c + 1];
            float* d = acc[mt][nt];
            d[0] += bb + (1.0f - pm0 * hm0) * NEGINF;
            d[1] += bb + (1.0f - pm0 * hm1) * NEGINF;
            d[2] += bb + (1.0f - pm1 * hm0) * NEGINF;
            d[3] += bb + (1.0f - pm1 * hm1) * NEGINF;
            *(float2*)&g_sim[((size_t)b * LL + r0) * LL + c] = make_float2(d[0], d[1]);
            *(float2*)&g_sim[((size_t)b * LL + r1) * LL + c] = make_float2(d[2], d[3]);
        }
    }

    // ---- fused stats partials (reuse smem as float scratch) ----
    float* S = (float*)sm;
    float* rowmS = S;            // [4][128]
    float* rowsS = S + 512;      // [4][128]
    float* colmS = S + 1024;     // [2][128]
    const int wng = warp & 3, wrow = warp >> 2;
    __syncthreads();

#pragma unroll
    for (int mt = 0; mt < 4; mt++) {
        float m0 = FLT_LOW, m1 = FLT_LOW;
#pragma unroll
        for (int nt = 0; nt < 4; nt++) {
            m0 = fmaxf(m0, fmaxf(acc[mt][nt][0], acc[mt][nt][1]));
            m1 = fmaxf(m1, fmaxf(acc[mt][nt][2], acc[mt][nt][3]));
        }
        m0 = fmaxf(m0, __shfl_xor_sync(0xffffffffu, m0, 1));
        m0 = fmaxf(m0, __shfl_xor_sync(0xffffffffu, m0, 2));
        m1 = fmaxf(m1, __shfl_xor_sync(0xffffffffu, m1, 1));
        m1 = fmaxf(m1, __shfl_xor_sync(0xffffffffu, m1, 2));
        if (tig == 0) {
            rowmS[wng * 128 + wm + mt * 16 + gid]     = m0;
            rowmS[wng * 128 + wm + mt * 16 + gid + 8] = m1;
        }
    }
#pragma unroll
    for (int nt = 0; nt < 4; nt++) {
        float c0 = FLT_LOW, c1 = FLT_LOW;
#pragma unroll
        for (int mt = 0; mt < 4; mt++) {
            c0 = fmaxf(c0, fmaxf(acc[mt][nt][0], acc[mt][nt][2]));
            c1 = fmaxf(c1, fmaxf(acc[mt][nt][1], acc[mt][nt][3]));
        }
        c0 = fmaxf(c0, __shfl_xor_sync(0xffffffffu, c0, 4));
        c0 = fmaxf(c0, __shfl_xor_sync(0xffffffffu, c0, 8));
        c0 = fmaxf(c0, __shfl_xor_sync(0xffffffffu, c0, 16));
        c1 = fmaxf(c1, __shfl_xor_sync(0xffffffffu, c1, 4));
        c1 = fmaxf(c1, __shfl_xor_sync(0xffffffffu, c1, 8));
        c1 = fmaxf(c1, __shfl_xor_sync(0xffffffffu, c1, 16));
        if (gid == 0) {
            colmS[wrow * 128 + wn + nt * 8 + tig * 2]     = c0;
            colmS[wrow * 128 + wn + nt * 8 + tig * 2 + 1] = c1;
        }
    }
    __syncthreads();

#pragma unroll
    for (int mt = 0; mt < 4; mt++) {
        int lr0 = wm + mt * 16 + gid, lr1 = lr0 + 8;
        float m0 = fmaxf(fmaxf(rowmS[lr0], rowmS[128 + lr0]),
                         fmaxf(rowmS[256 + lr0], rowmS[384 + lr0]));
        float m1 = fmaxf(fmaxf(rowmS[lr1], rowmS[128 + lr1]),
                         fmaxf(rowmS[256 + lr1], rowmS[384 + lr1]));
        float s0 = 0.0f, s1 = 0.0f;
#pragma unroll
        for (int nt = 0; nt < 4; nt++) {
            s0 += __expf(acc[mt][nt][0] - m0) + __expf(acc[mt][nt][1] - m0);
            s1 += __expf(acc[mt][nt][2] - m1) + __expf(acc[mt][nt][3] - m1);
        }
        s0 += __shfl_xor_sync(0xffffffffu, s0, 1);
        s0 += __shfl_xor_sync(0xffffffffu, s0, 2);
        s1 += __shfl_xor_sync(0xffffffffu, s1, 1);
        s1 += __shfl_xor_sync(0xffffffffu, s1, 2);
        if (tig == 0) {
            rowsS[wng * 128 + lr0] = s0;
            rowsS[wng * 128 + lr1] = s1;
        }
    }
    __syncthreads();

    if (tid < 128) {
        float m = fmaxf(fmaxf(rowmS[tid], rowmS[128 + tid]),
                        fmaxf(rowmS[256 + tid], rowmS[384 + tid]));
        float s = rowsS[tid] + rowsS[128 + tid] + rowsS[256 + tid] + rowsS[384 + tid];
        size_t ro = (size_t)blockIdx.x * (NB * LL) + (size_t)b * LL + bm + tid;
        g_rowpm[ro] = m;
        g_rowps[ro] = s;
        float cm = fmaxf(colmS[tid], colmS[128 + tid]);
        g_colpart[((size_t)b * 8 + blockIdx.y) * LL + bn + tid] = cm;
    }
}

// =============================================================================
// Kernel C2: combine 8 row partials -> rowmax / rowinv
// =============================================================================
__global__ void k_finstats() {
    int row = blockIdx.x * 256 + threadIdx.x;     // < NB*LL
    float mj[8];
    float m = FLT_LOW;
#pragma unroll
    for (int j = 0; j < 8; j++) {
        mj[j] = g_rowpm[j * (NB * LL) + row];
        m = fmaxf(m, mj[j]);
    }
    float s = 0.0f;
#pragma unroll
    for (int j = 0; j < 8; j++)
        s += g_rowps[j * (NB * LL) + row] * __expf(mj[j] - m);
    g_rowmax[row] = m;
    g_rowinv[row] = 1.0f / s;
}

// =============================================================================
// Kernel D: aligned_hyp[b] = softmax(sim[b]) @ H[b]  (cp.async, ldmatrix.trans)
// =============================================================================
#define AV_AH 0
#define AV_AL 5120
#define AV_B(s) (10240 + (s) * 8704)
#define AV_SRAW_H 27648
#define AV_SMEM_BYTES (55296 + 2 * 128 * 36 * 4)

__global__ __launch_bounds__(256, 2) void k_av(float* __restrict__ out) {
    extern __shared__ __align__(16) __nv_bfloat16 sm[];
    float* Sraw = (float*)(sm + AV_SRAW_H);
    const int b = blockIdx.z;
    const int bm = blockIdx.y * 128, bn = blockIdx.x * 128;   // bn over DH
    const int tid = threadIdx.x, warp = tid >> 5, lane = tid & 31;
    const int wm = (warp >> 2) * 64, wn = (warp & 3) * 32;
    const int gid = lane >> 2, tig = lane & 3;
    const int lrow = tid >> 1, lseg = (tid & 1) * 16;
    const int arow = wm + (lane & 15), acol = (lane >> 4) * 8;
    const int tkr = (lane & 7) + ((lane >> 3) & 1) * 8;
    const int tdc = ((lane >> 4) & 1) * 8;
    const int qr = tid >> 3, dc = (tid & 7) * 16;

    const float rm = g_rowmax[b * LL + bm + lrow];
    const float ri = g_rowinv[b * LL + bm + lrow];
    const float* sp = &g_sim[((size_t)b * LL + bm + lrow) * LL + lseg];

    float acc[4][4][4];
#pragma unroll
    for (int mt = 0; mt < 4; mt++)
#pragma unroll
        for (int nt = 0; nt < 4; nt++)
#pragma unroll
            for (int e = 0; e < 4; e++) acc[mt][nt][e] = 0.0f;

    {
        float* sr = Sraw + lrow * 36 + lseg;
        cpa16(sr,      sp);
        cpa16(sr + 4,  sp + 4);
        cpa16(sr + 8,  sp + 8);
        cpa16(sr + 12, sp + 12);
        size_t hb = ((size_t)b * LL + qr) * DH + bn + dc;
        __nv_bfloat16* bh = sm + AV_B(0) + qr * 136 + dc;
        cpa16(bh,            &g_Hhi[hb]);
        cpa16(bh + 8,        &g_Hhi[hb + 8]);
        cpa16(bh + 4352,     &g_Hlo[hb]);
        cpa16(bh + 4352 + 8, &g_Hlo[hb + 8]);
        CP_COMMIT;
    }
    int s = 0;
    for (int k0 = 0; k0 < LL; k0 += 32, s ^= 1) {
        CP_WAIT0;
        __syncthreads();
        if (k0 + 32 < LL) {
            float* sr = Sraw + (s ^ 1) * 128 * 36 + lrow * 36 + lseg;
            const float* spn = sp + k0 + 32;
            cpa16(sr,      spn);
            cpa16(sr + 4,  spn + 4);
            cpa16(sr + 8,  spn + 8);
            cpa16(sr + 12, spn + 12);
            size_t hb = ((size_t)b * LL + k0 + 32 + qr) * DH + bn + dc;
            __nv_bfloat16* bh = sm + AV_B(s ^ 1) + qr * 136 + dc;
            cpa16(bh,            &g_Hhi[hb]);
            cpa16(bh + 8,        &g_Hhi[hb + 8]);
            cpa16(bh + 4352,     &g_Hlo[hb]);
            cpa16(bh + 4352 + 8, &g_Hlo[hb + 8]);
            CP_COMMIT;
        }
        {
            const float* sr = Sraw + s * 128 * 36 + lrow * 36 + lseg;
            BF8 phi0, phi1, plo0, plo1;
#pragma unroll
            for (int i = 0; i < 8; i++) {
                float p0 = __expf(sr[i] - rm) * ri;
                float p1 = __expf(sr[8 + i] - rm) * ri;
                split_bf16(p0, phi0.h[i], plo0.h[i]);
                split_bf16(p1, phi1.h[i], plo1.h[i]);
            }
            *(uint4*)(sm + AV_AH + lrow * 40 + lseg)     = phi0.v;
            *(uint4*)(sm + AV_AH + lrow * 40 + lseg + 8) = phi1.v;
            *(uint4*)(sm + AV_AL + lrow * 40 + lseg)     = plo0.v;
            *(uint4*)(sm + AV_AL + lrow * 40 + lseg + 8) = plo1.v;
        }
        __syncthreads();
        const __nv_bfloat16* Bhs = sm + AV_B(s);
        const __nv_bfloat16* Bls = Bhs + 4352;
#pragma unroll
        for (int ks = 0; ks < 32; ks += 16) {
            unsigned afh[4][4], afl[4][4];
#pragma unroll
            for (int mt = 0; mt < 4; mt++) {
                ldsm4(afh[mt], sm32(sm + AV_AH + (arow + mt * 16) * 40 + ks + acol));
                ldsm4(afl[mt], sm32(sm + AV_AL + (arow + mt * 16) * 40 + ks + acol));
            }
#pragma unroll
            for (int p = 0; p < 2; p++) {
                unsigned bh4[4], bl4[4];
                ldsm4t(bh4, sm32(Bhs + (ks + tkr) * 136 + wn + p * 16 + tdc));
                ldsm4t(bl4, sm32(Bls + (ks + tkr) * 136 + wn + p * 16 + tdc));
#pragma unroll
                for (int mt = 0; mt < 4; mt++)
#pragma unroll
                    for (int q = 0; q < 2; q++)
                        mma_bf16(acc[mt][p * 2 + q], afh[mt], &bh4[2 * q]);
#pragma unroll
                for (int mt = 0; mt < 4; mt++)
#pragma unroll
                    for (int q = 0; q < 2; q++)
                        mma_bf16(acc[mt][p * 2 + q], afh[mt], &bl4[2 * q]);
#pragma unroll
                for (int mt = 0; mt < 4; mt++)
#pragma unroll
                    for (int q = 0; q < 2; q++)
                        mma_bf16(acc[mt][p * 2 + q], afl[mt], &bh4[2 * q]);
            }
        }
    }
#pragma unroll
    for (int mt = 0; mt < 4; mt++) {
        int r0 = bm + wm + mt * 16 + gid, r1 = r0 + 8;
#pragma unroll
        for (int nt = 0; nt < 4; nt++) {
            int c = bn + wn + nt * 8 + tig * 2;
            float* d = acc[mt][nt];
            *(float2*)&out[((size_t)b * LL + r0) * DH + c] = make_float2(d[0], d[1]);
            *(float2*)&out[((size_t)b * LL + r1) * DH + c] = make_float2(d[2], d[3]);
        }
    }
}

// =============================================================================
// Kernel E: per batch — softmax(colmax over 8 partials) @ P -> g_pvec
// =============================================================================
__global__ __launch_bounds__(256) void k_premise(const float* __restrict__ P) {
    const int b = blockIdx.x;
    const int t = threadIdx.x;
    __shared__ float prob[LL];
    __shared__ float red[8];
    float loc[4];
#pragma unroll
    for (int c = 0; c < 4; c++) {
        int q = c * 256 + t;
        float m = FLT_LOW;
#pragma unroll
        for (int j = 0; j < 8; j++)
            m = fmaxf(m, g_colpart[((size_t)b * 8 + j) * LL + q]);
        loc[c] = m;
    }
    float mx = fmaxf(fmaxf(loc[0], loc[1]), fmaxf(loc[2], loc[3]));
#pragma unroll
    for (int o = 16; o > 0; o >>= 1) mx = fmaxf(mx, __shfl_xor_sync(0xffffffffu, mx, o));
    const int w = t >> 5, lane = t & 31;
    if (lane == 0) red[w] = mx;
    __syncthreads();
    mx = red[0];
#pragma unroll
    for (int j = 1; j < 8; j++) mx = fmaxf(mx, red[j]);

    float se = 0.0f;
#pragma unroll
    for (int c = 0; c < 4; c++) {
        float e = __expf(loc[c] - mx);
        prob[c * 256 + t] = e;
        se += e;
    }
#pragma unroll
    for (int o = 16; o > 0; o >>= 1) se += __shfl_xor_sync(0xffffffffu, se, o);
    __syncthreads();
    if (lane == 0) red[w] = se;
    __syncthreads();
    float tot = 0.0f;
#pragma unroll
    for (int j = 0; j < 8; j++) tot += red[j];
    const float inv = 1.0f / tot;

    const float* Pb = P + (size_t)b * LL * DH + t;
    float acc = 0.0f;
#pragma unroll 8
    for (int q = 0; q < LL; q++)
        acc = fmaf(prob[q], Pb[(size_t)q * DH], acc);
    g_pvec[b * DH + t] = acc * inv;
}

// =============================================================================
// Kernel F: broadcast g_pvec -> out[0 : NB*LL*DH)
// =============================================================================
__global__ void k_bcast(float* __restrict__ out) {
    int idx = (blockIdx.x * 256 + threadIdx.x) * 4;
    int b = idx >> 18;
    int d = idx & (DH - 1);
    float4 v = *(const float4*)&g_pvec[b * DH + d];
    *(float4*)&out[idx] = v;
}

// =============================================================================
extern "C" void kernel_launch(void* const* d_in, const int* in_sizes, int n_in,
                              void* d_out, int out_size) {
    const float* P    = (const float*)d_in[0];
    const float* Hh   = (const float*)d_in[1];
    const int*   pm   = (const int*)d_in[2];
    const int*   hm   = (const int*)d_in[3];
    const float* W    = (const float*)d_in[4];
    const float* bias = (const float*)d_in[5];
    float* out = (float*)d_out;

    const int gemm_smem = 2 * STG * 2;            // 81920 bytes
    cudaFuncSetAttribute(k_pw_mma, cudaFuncAttributeMaxDynamicSharedMemorySize, gemm_smem);
    cudaFuncSetAttribute(k_sim,    cudaFuncAttributeMaxDynamicSharedMemorySize, gemm_smem);
    cudaFuncSetAttribute(k_av,     cudaFuncAttributeMaxDynamicSharedMemorySize, AV_SMEM_BYTES);

    k_cvtH     <<<(NB * LL * DH) / (256 * 4), 256>>>(Hh);
    k_cvtP     <<<(NB * LL * DH) / (256 * 4), 256>>>(P);
    k_cvtW     <<<DH * DH / 256, 256>>>(W);
    k_pw_mma   <<<dim3(DH / 128, (NB * LL) / 128), 256, gemm_smem>>>();
    k_sim      <<<dim3(LL / 128, LL / 128, NB), 256, gemm_smem>>>(pm, hm, bias);
    k_finstats <<<(NB * LL) / 256, 256>>>();
    k_av       <<<dim3(DH / 128, LL / 128, NB), 256, AV_SMEM_BYTES>>>(out + (size_t)NB * LL * DH);
    k_premise  <<<NB, 256>>>(P);
    k_bcast    <<<(NB * LL * DH) / (256 * 4), 256>>>(out);
}